// round 1
// baseline (speedup 1.0000x reference)
#include <cuda_runtime.h>
#include <math.h>

// Problem constants
#define B_   8
#define S_   1024
#define D_   768
#define H_   12
#define HD_  64
#define MTOT (B_ * S_)   // 8192

// ---------------------------------------------------------------------------
// Scratch (device globals — no runtime allocation allowed)
// ---------------------------------------------------------------------------
__device__ float g_q[(size_t)B_ * H_ * S_ * HD_];    // [BH, S, Hd]
__device__ float g_k[(size_t)B_ * H_ * S_ * HD_];
__device__ float g_v[(size_t)B_ * H_ * S_ * HD_];
__device__ float g_attn[(size_t)MTOT * D_];          // [M, D] row-major

// ---------------------------------------------------------------------------
// SGEMM: C[M,N] = A[M,K] @ W[K,N] + bias,  M=8192, N=K=768 (exact tiles)
// 128x128 block tile, BK=16, 256 threads, 8x8 per-thread micro-tile.
// OUT_QKV=1 scatters output to [B,H,S,Hd]; OUT_QKV=0 writes row-major [M,N].
// ---------------------------------------------------------------------------
template <int OUT_QKV>
__global__ __launch_bounds__(256)
void sgemm_kernel(const float* __restrict__ A, const float* __restrict__ W,
                  const float* __restrict__ bias, float* __restrict__ out)
{
    constexpr int K = D_, N = D_;
    __shared__ float As[128][16];   // row-major [m][k]
    __shared__ float Bs[16][128];   // row-major [k][n]

    const int tid = threadIdx.x;
    const int tx  = tid & 15;      // column group: 8 cols at tx*8
    const int ty  = tid >> 4;      // row group:    8 rows at ty*8
    const int m0  = blockIdx.y * 128;
    const int n0  = blockIdx.x * 128;

    float acc[8][8];
#pragma unroll
    for (int i = 0; i < 8; i++)
#pragma unroll
        for (int j = 0; j < 8; j++) acc[i][j] = 0.0f;

    for (int kt = 0; kt < K; kt += 16) {
        // Load A tile 128x16 (2 float4 per thread)
#pragma unroll
        for (int i = 0; i < 2; i++) {
            int f  = tid + i * 256;
            int r  = f >> 2;            // 0..127
            int kk = (f & 3) << 2;      // 0,4,8,12
            *(float4*)&As[r][kk] =
                *(const float4*)(A + (size_t)(m0 + r) * K + kt + kk);
        }
        // Load B tile 16x128 (2 float4 per thread)
#pragma unroll
        for (int i = 0; i < 2; i++) {
            int f = tid + i * 256;
            int r = f >> 5;             // 0..15
            int c = (f & 31) << 2;      // 0..124
            *(float4*)&Bs[r][c] =
                *(const float4*)(W + (size_t)(kt + r) * N + n0 + c);
        }
        __syncthreads();

#pragma unroll
        for (int k0 = 0; k0 < 16; k0 += 4) {
            float4 a4[8];
#pragma unroll
            for (int i = 0; i < 8; i++)
                a4[i] = *(const float4*)&As[ty * 8 + i][k0];
#pragma unroll
            for (int kk = 0; kk < 4; kk++) {
                float4 b0 = *(const float4*)&Bs[k0 + kk][tx * 8];
                float4 b1 = *(const float4*)&Bs[k0 + kk][tx * 8 + 4];
#pragma unroll
                for (int i = 0; i < 8; i++) {
                    float a = ((const float*)&a4[i])[kk];
                    acc[i][0] += a * b0.x;  acc[i][1] += a * b0.y;
                    acc[i][2] += a * b0.z;  acc[i][3] += a * b0.w;
                    acc[i][4] += a * b1.x;  acc[i][5] += a * b1.y;
                    acc[i][6] += a * b1.z;  acc[i][7] += a * b1.w;
                }
            }
        }
        __syncthreads();
    }

    // Epilogue
#pragma unroll
    for (int i = 0; i < 8; i++) {
        int m = m0 + ty * 8 + i;
#pragma unroll
        for (int j0 = 0; j0 < 8; j0 += 4) {
            int n = n0 + tx * 8 + j0;
            float4 v;
            v.x = acc[i][j0 + 0] + bias[n + 0];
            v.y = acc[i][j0 + 1] + bias[n + 1];
            v.z = acc[i][j0 + 2] + bias[n + 2];
            v.w = acc[i][j0 + 3] + bias[n + 3];
            if (OUT_QKV) {
                int b = m >> 10, s = m & 1023;
                int h = n >> 6,  d = n & 63;
                *(float4*)(out + (((size_t)(b * H_ + h) * S_ + s) * HD_ + d)) = v;
            } else {
                *(float4*)(out + (size_t)m * N + n) = v;
            }
        }
    }
}

// ---------------------------------------------------------------------------
// Flash attention (fp32): one block per (batch, head, 128-query tile).
// 256 threads: tx (16) owns 4 of 64 output cols, ty (16) owns 8 of 128 rows.
// K/V streamed in 64-row tiles; online softmax; all smem traffic is float4
// on 68-float-stride rows (16B-aligned, conflict-light).
// ---------------------------------------------------------------------------
#define QS_STRIDE 68
#define ATTN_SMEM ((128 * QS_STRIDE + 64 * QS_STRIDE + 64 * QS_STRIDE + 128 * QS_STRIDE) * (int)sizeof(float))

__global__ __launch_bounds__(256)
void attn_kernel(const float* __restrict__ Q, const float* __restrict__ K,
                 const float* __restrict__ V, float* __restrict__ O)
{
    extern __shared__ float sm[];
    float* Qs = sm;                         // [128][68]
    float* Ks = Qs + 128 * QS_STRIDE;       // [64][68]
    float* Vs = Ks + 64 * QS_STRIDE;        // [64][68]
    float* Ps = Vs + 64 * QS_STRIDE;        // [128][68]

    const int tid = threadIdx.x;
    const int tx  = tid & 15;               // cols tx*4 .. tx*4+3
    const int ty  = tid >> 4;               // rows ty*8 .. ty*8+7
    const int bh  = blockIdx.z * H_ + blockIdx.y;
    const int q0  = blockIdx.x * 128;

    const float* qptr  = Q + ((size_t)bh * S_ + q0) * HD_;
    const float* kbase = K + (size_t)bh * S_ * HD_;
    const float* vbase = V + (size_t)bh * S_ * HD_;

    // Load Q tile 128x64 (8 float4 per thread)
#pragma unroll
    for (int i = 0; i < 8; i++) {
        int f = tid + i * 256;
        int r = f >> 4;                 // 0..127
        int d = (f & 15) << 2;          // 0..60
        *(float4*)&Qs[r * QS_STRIDE + d] = *(const float4*)(qptr + (size_t)r * HD_ + d);
    }

    float m_i[8], l_i[8], acc[8][4];
#pragma unroll
    for (int i = 0; i < 8; i++) {
        m_i[i] = -1e30f; l_i[i] = 0.0f;
#pragma unroll
        for (int c = 0; c < 4; c++) acc[i][c] = 0.0f;
    }

    for (int kt = 0; kt < S_; kt += 64) {
        __syncthreads();   // protect Ks/Vs from previous iteration's readers
        // Load K,V tiles 64x64 (4 float4 each per thread)
#pragma unroll
        for (int i = 0; i < 4; i++) {
            int f = tid + i * 256;
            int r = f >> 4;
            int d = (f & 15) << 2;
            *(float4*)&Ks[r * QS_STRIDE + d] =
                *(const float4*)(kbase + (size_t)(kt + r) * HD_ + d);
            *(float4*)&Vs[r * QS_STRIDE + d] =
                *(const float4*)(vbase + (size_t)(kt + r) * HD_ + d);
        }
        __syncthreads();

        // S = Q @ K^T  (8 rows x 4 cols per thread)
        float s[8][4];
#pragma unroll
        for (int i = 0; i < 8; i++)
#pragma unroll
            for (int c = 0; c < 4; c++) s[i][c] = 0.0f;

#pragma unroll
        for (int d0 = 0; d0 < HD_; d0 += 4) {
            float4 qv[8], kv[4];
#pragma unroll
            for (int i = 0; i < 8; i++)
                qv[i] = *(const float4*)&Qs[(ty * 8 + i) * QS_STRIDE + d0];
#pragma unroll
            for (int c = 0; c < 4; c++)
                kv[c] = *(const float4*)&Ks[(tx * 4 + c) * QS_STRIDE + d0];
#pragma unroll
            for (int i = 0; i < 8; i++)
#pragma unroll
                for (int c = 0; c < 4; c++)
                    s[i][c] += qv[i].x * kv[c].x + qv[i].y * kv[c].y +
                               qv[i].z * kv[c].z + qv[i].w * kv[c].w;
        }

        // Online softmax update per row (state replicated across the 16 tx lanes)
#pragma unroll
        for (int i = 0; i < 8; i++) {
            float mx = -1e30f;
#pragma unroll
            for (int c = 0; c < 4; c++) { s[i][c] *= 0.125f; mx = fmaxf(mx, s[i][c]); }
#pragma unroll
            for (int off = 8; off >= 1; off >>= 1)
                mx = fmaxf(mx, __shfl_xor_sync(0xffffffffu, mx, off));
            float mnew = fmaxf(m_i[i], mx);
            float corr = __expf(m_i[i] - mnew);
            m_i[i] = mnew;
            float rs = 0.0f;
#pragma unroll
            for (int c = 0; c < 4; c++) {
                float p = __expf(s[i][c] - mnew);
                s[i][c] = p; rs += p;
            }
#pragma unroll
            for (int off = 8; off >= 1; off >>= 1)
                rs += __shfl_xor_sync(0xffffffffu, rs, off);
            l_i[i] = l_i[i] * corr + rs;
#pragma unroll
            for (int c = 0; c < 4; c++) acc[i][c] *= corr;
            // Write P (row-major, float4)
            *(float4*)&Ps[(ty * 8 + i) * QS_STRIDE + tx * 4] = *(float4*)&s[i][0];
        }
        __syncthreads();

        // O += P @ V
#pragma unroll
        for (int j0 = 0; j0 < 64; j0 += 4) {
            float4 pv[8], vv[4];
#pragma unroll
            for (int i = 0; i < 8; i++)
                pv[i] = *(const float4*)&Ps[(ty * 8 + i) * QS_STRIDE + j0];
#pragma unroll
            for (int jj = 0; jj < 4; jj++)
                vv[jj] = *(const float4*)&Vs[(j0 + jj) * QS_STRIDE + tx * 4];
#pragma unroll
            for (int i = 0; i < 8; i++) {
                acc[i][0] += pv[i].x * vv[0].x + pv[i].y * vv[1].x + pv[i].z * vv[2].x + pv[i].w * vv[3].x;
                acc[i][1] += pv[i].x * vv[0].y + pv[i].y * vv[1].y + pv[i].z * vv[2].y + pv[i].w * vv[3].y;
                acc[i][2] += pv[i].x * vv[0].z + pv[i].y * vv[1].z + pv[i].z * vv[2].z + pv[i].w * vv[3].z;
                acc[i][3] += pv[i].x * vv[0].w + pv[i].y * vv[1].w + pv[i].z * vv[2].w + pv[i].w * vv[3].w;
            }
        }
    }

    // Normalize and write to attn buffer [M, D] at columns h*64 + tx*4
    const int b = blockIdx.z, h = blockIdx.y;
#pragma unroll
    for (int i = 0; i < 8; i++) {
        float inv = 1.0f / l_i[i];
        float4 o;
        o.x = acc[i][0] * inv; o.y = acc[i][1] * inv;
        o.z = acc[i][2] * inv; o.w = acc[i][3] * inv;
        size_t row = (size_t)b * S_ + q0 + ty * 8 + i;
        *(float4*)(O + row * D_ + h * HD_ + tx * 4) = o;
    }
}

// ---------------------------------------------------------------------------
// Launch
// ---------------------------------------------------------------------------
extern "C" void kernel_launch(void* const* d_in, const int* in_sizes, int n_in,
                              void* d_out, int out_size)
{
    const float* x  = (const float*)d_in[0];
    const float* wq = (const float*)d_in[1];
    const float* bq = (const float*)d_in[2];
    const float* wk = (const float*)d_in[3];
    const float* bk = (const float*)d_in[4];
    const float* wv = (const float*)d_in[5];
    const float* bv = (const float*)d_in[6];
    const float* wo = (const float*)d_in[7];
    const float* bo = (const float*)d_in[8];
    float* out = (float*)d_out;

    float *qp, *kp, *vp, *ap;
    cudaGetSymbolAddress((void**)&qp, g_q);
    cudaGetSymbolAddress((void**)&kp, g_k);
    cudaGetSymbolAddress((void**)&vp, g_v);
    cudaGetSymbolAddress((void**)&ap, g_attn);

    cudaFuncSetAttribute(attn_kernel,
                         cudaFuncAttributeMaxDynamicSharedMemorySize, ATTN_SMEM);

    dim3 gemm_grid(D_ / 128, MTOT / 128);   // (6, 64)

    sgemm_kernel<1><<<gemm_grid, 256>>>(x, wq, bq, qp);
    sgemm_kernel<1><<<gemm_grid, 256>>>(x, wk, bk, kp);
    sgemm_kernel<1><<<gemm_grid, 256>>>(x, wv, bv, vp);

    attn_kernel<<<dim3(S_ / 128, H_, B_), 256, ATTN_SMEM>>>(qp, kp, vp, ap);

    sgemm_kernel<0><<<gemm_grid, 256>>>(ap, wo, bo, out);
}

// round 4
// speedup vs baseline: 1.4721x; 1.4721x over previous
#include <cuda_runtime.h>
#include <cuda_bf16.h>
#include <math.h>
#include <stdint.h>

// Problem constants
#define B_   8
#define S_   1024
#define D_   768
#define H_   12
#define HD_  64
#define MTOT (B_ * S_)       // 8192
#define KP_  (3 * D_)        // 2304 : [hi | hi | lo] split-K

// ---------------------------------------------------------------------------
// Scratch (device globals — no runtime allocation allowed)
// ---------------------------------------------------------------------------
__device__ float g_q[(size_t)B_ * H_ * S_ * HD_];
__device__ float g_k[(size_t)B_ * H_ * S_ * HD_];
__device__ float g_v[(size_t)B_ * H_ * S_ * HD_];
__device__ float g_attn[(size_t)MTOT * D_];
__device__ __nv_bfloat16 g_ax[(size_t)MTOT * KP_];    // split(x)
__device__ __nv_bfloat16 g_a2[(size_t)MTOT * KP_];    // split(attn)
__device__ __nv_bfloat16 g_wq[(size_t)D_ * KP_];      // split(W^T) [n, k']
__device__ __nv_bfloat16 g_wk[(size_t)D_ * KP_];
__device__ __nv_bfloat16 g_wv[(size_t)D_ * KP_];
__device__ __nv_bfloat16 g_wo[(size_t)D_ * KP_];

// ---------------------------------------------------------------------------
// PTX helpers (standard sm_80+ instructions only — NO tcgen05 on this target)
// ---------------------------------------------------------------------------
__device__ __forceinline__ uint32_t smem_u32(const void* p) {
    uint32_t a;
    asm("{ .reg .u64 t; cvta.to.shared.u64 t, %1; cvt.u32.u64 %0, t; }" : "=r"(a) : "l"(p));
    return a;
}
__device__ __forceinline__ void cp_async16(uint32_t dst, const void* src) {
    asm volatile("cp.async.cg.shared.global [%0], [%1], 16;" :: "r"(dst), "l"(src) : "memory");
}
__device__ __forceinline__ void cp_commit() {
    asm volatile("cp.async.commit_group;" ::: "memory");
}
template <int N>
__device__ __forceinline__ void cp_wait() {
    asm volatile("cp.async.wait_group %0;" :: "n"(N) : "memory");
}
__device__ __forceinline__ void ldmatrix_x4(uint32_t* r, uint32_t addr) {
    asm volatile("ldmatrix.sync.aligned.m8n8.x4.shared.b16 {%0,%1,%2,%3}, [%4];"
        : "=r"(r[0]), "=r"(r[1]), "=r"(r[2]), "=r"(r[3]) : "r"(addr));
}
__device__ __forceinline__ void mma_bf16(float* c, const uint32_t* a, const uint32_t* b) {
    asm volatile(
        "mma.sync.aligned.m16n8k16.row.col.f32.bf16.bf16.f32 "
        "{%0,%1,%2,%3}, {%4,%5,%6,%7}, {%8,%9}, {%0,%1,%2,%3};"
        : "+f"(c[0]), "+f"(c[1]), "+f"(c[2]), "+f"(c[3])
        : "r"(a[0]), "r"(a[1]), "r"(a[2]), "r"(a[3]), "r"(b[0]), "r"(b[1]));
}

// SW128 swizzle for 128B rows (16B-chunk granularity)
#define SW128(off) ((off) ^ (((off) >> 3) & 0x70))

// ---------------------------------------------------------------------------
// Split kernels: fp32 -> bf16 hi/lo packed K' = [hi | hi | lo] (A)
//                                            [hi | lo | hi] (W^T)
// ---------------------------------------------------------------------------
__global__ __launch_bounds__(256) void split_a_kernel(const float* __restrict__ in,
                                                      __nv_bfloat16* __restrict__ out)
{
    int idx = blockIdx.x * blockDim.x + threadIdx.x;   // one per 4 elements
    int m  = idx / (D_ / 4);
    int k4 = (idx % (D_ / 4)) * 4;
    float4 x = *(const float4*)(in + (size_t)m * D_ + k4);
    float xs[4] = {x.x, x.y, x.z, x.w};
    __nv_bfloat16 hi[4], lo[4];
#pragma unroll
    for (int i = 0; i < 4; i++) {
        hi[i] = __float2bfloat16(xs[i]);
        lo[i] = __float2bfloat16(xs[i] - __bfloat162float(hi[i]));
    }
    uint2 hp, lp;
    ((__nv_bfloat162*)&hp)[0] = __nv_bfloat162(hi[0], hi[1]);
    ((__nv_bfloat162*)&hp)[1] = __nv_bfloat162(hi[2], hi[3]);
    ((__nv_bfloat162*)&lp)[0] = __nv_bfloat162(lo[0], lo[1]);
    ((__nv_bfloat162*)&lp)[1] = __nv_bfloat162(lo[2], lo[3]);
    __nv_bfloat16* row = out + (size_t)m * KP_;
    *(uint2*)(row + k4)            = hp;   // hi
    *(uint2*)(row + D_ + k4)       = hp;   // hi
    *(uint2*)(row + 2 * D_ + k4)   = lp;   // lo
}

// W [K=768, N=768] fp32 -> W' bf16 [n, k'] with parts [hi | lo | hi]
__global__ __launch_bounds__(256) void split_w_kernel(const float* __restrict__ w,
                                                      __nv_bfloat16* __restrict__ out)
{
    int idx = blockIdx.x * blockDim.x + threadIdx.x;
    int n  = idx / (D_ / 4);
    int k4 = (idx % (D_ / 4)) * 4;
    __nv_bfloat16 hi[4], lo[4];
#pragma unroll
    for (int i = 0; i < 4; i++) {
        float x = w[(size_t)(k4 + i) * D_ + n];
        hi[i] = __float2bfloat16(x);
        lo[i] = __float2bfloat16(x - __bfloat162float(hi[i]));
    }
    uint2 hp, lp;
    ((__nv_bfloat162*)&hp)[0] = __nv_bfloat162(hi[0], hi[1]);
    ((__nv_bfloat162*)&hp)[1] = __nv_bfloat162(hi[2], hi[3]);
    ((__nv_bfloat162*)&lp)[0] = __nv_bfloat162(lo[0], lo[1]);
    ((__nv_bfloat162*)&lp)[1] = __nv_bfloat162(lo[2], lo[3]);
    __nv_bfloat16* row = out + (size_t)n * KP_;
    *(uint2*)(row + k4)          = hp;   // hi
    *(uint2*)(row + D_ + k4)     = lp;   // lo
    *(uint2*)(row + 2 * D_ + k4) = hp;   // hi
}

// ---------------------------------------------------------------------------
// mma.sync GEMM: C[M, N=768] = A'[M, KP_] @ W'^T + bias.
// CTA: 128(m) x 128(n), BK=64, double-buffered cp.async, SW128 smem,
// 8 warps (2m x 4n), warp tile 64x32, mma.m16n8k16 bf16 -> fp32.
// OUT_QKV=1 scatters to [B,H,S,Hd]; else row-major [M, 768].
// ---------------------------------------------------------------------------
#define BK_        64
#define NT_        (KP_ / BK_)            // 36
#define TILE_B     (128 * 128)            // 16KB: one 128x(64 bf16) tile
#define GEMM_SMEM  (4 * TILE_B)           // 64KB (2 stages x (A+B))

template <int OUT_QKV>
__global__ __launch_bounds__(256)
void tc_gemm_kernel(const __nv_bfloat16* __restrict__ A,
                    const __nv_bfloat16* __restrict__ W,
                    const float* __restrict__ bias, float* __restrict__ out)
{
    extern __shared__ char smem_raw[];
    const uint32_t sbase = smem_u32(smem_raw);
    const int tid  = threadIdx.x;
    const int wid  = tid >> 5;
    const int lane = tid & 31;
    const int wm   = (wid & 1) * 64;      // warp m offset in tile
    const int wn   = (wid >> 1) * 32;     // warp n offset in tile
    const int m0   = blockIdx.y * 128;
    const int n0   = blockIdx.x * 128;

    // load thread mapping: 2 threads per 128B row, 4 16B-chunks each (full row)
    const int lr = tid >> 1;                  // 0..127
    const int lc = (tid & 1) * 4;             // chunk 0 or 4

    float acc[4][4][4];
#pragma unroll
    for (int i = 0; i < 4; i++)
#pragma unroll
        for (int j = 0; j < 4; j++)
#pragma unroll
            for (int e = 0; e < 4; e++) acc[i][j][e] = 0.0f;

    auto load_stage = [&](int it, int s) {
        const uint32_t sA = sbase + s * 2 * TILE_B;
        const uint32_t sB = sA + TILE_B;
        const int k0 = it * BK_;
        const __nv_bfloat16* Ag = A + (size_t)(m0 + lr) * KP_ + k0 + lc * 8;
        const __nv_bfloat16* Wg = W + (size_t)(n0 + lr) * KP_ + k0 + lc * 8;
#pragma unroll
        for (int c = 0; c < 4; c++) {
            uint32_t off = SW128((uint32_t)(lr * 128 + (lc + c) * 16));
            cp_async16(sA + off, Ag + c * 8);
            cp_async16(sB + off, Wg + c * 8);
        }
    };

    // prologue
    load_stage(0, 0);
    cp_commit();

    // ldmatrix address components (per-lane, constant across stages)
    const int a_row = wm + (lane & 15);
    const int a_cb  = (lane >> 4) << 4;
    const int b_row = wn + (lane & 7) + ((lane >> 4) << 3);
    const int b_cb  = ((lane >> 3) & 1) << 4;

    for (int it = 0; it < NT_; it++) {
        const int s = it & 1;
        if (it + 1 < NT_) {
            load_stage(it + 1, s ^ 1);
            cp_commit();
            cp_wait<1>();
        } else {
            cp_wait<0>();
        }
        __syncthreads();

        const uint32_t sA = sbase + s * 2 * TILE_B;
        const uint32_t sB = sA + TILE_B;

#pragma unroll
        for (int ks = 0; ks < BK_ / 16; ks++) {
            uint32_t af[4][4], bf[2][4];
#pragma unroll
            for (int mt = 0; mt < 4; mt++) {
                uint32_t off = SW128((uint32_t)((a_row + mt * 16) * 128 + ks * 32 + a_cb));
                ldmatrix_x4(af[mt], sA + off);
            }
#pragma unroll
            for (int nt2 = 0; nt2 < 2; nt2++) {
                uint32_t off = SW128((uint32_t)((b_row + nt2 * 16) * 128 + ks * 32 + b_cb));
                ldmatrix_x4(bf[nt2], sB + off);
            }
#pragma unroll
            for (int mt = 0; mt < 4; mt++)
#pragma unroll
                for (int nt = 0; nt < 4; nt++)
                    mma_bf16(acc[mt][nt], af[mt], &bf[nt >> 1][(nt & 1) * 2]);
        }
        __syncthreads();
    }

    // epilogue: per (mt, nt) thread holds (m, n),(m, n+1),(m+8, n),(m+8, n+1)
#pragma unroll
    for (int mt = 0; mt < 4; mt++) {
#pragma unroll
        for (int nt = 0; nt < 4; nt++) {
            int m = m0 + wm + mt * 16 + (lane >> 2);
            int n = n0 + wn + nt * 8 + (lane & 3) * 2;
            float2 bv = *(const float2*)(bias + n);
            float2 v0 = {acc[mt][nt][0] + bv.x, acc[mt][nt][1] + bv.y};
            float2 v1 = {acc[mt][nt][2] + bv.x, acc[mt][nt][3] + bv.y};
            if (OUT_QKV) {
                int b = m >> 10, sq = m & 1023;
                int h = n >> 6, d = n & 63;
                size_t base0 = (((size_t)(b * H_ + h) * S_ + sq) * HD_ + d);
                *(float2*)(out + base0) = v0;
                *(float2*)(out + base0 + 8 * HD_) = v1;     // m+8 same b, sq+8
            } else {
                *(float2*)(out + (size_t)m * D_ + n) = v0;
                *(float2*)(out + (size_t)(m + 8) * D_ + n) = v1;
            }
        }
    }
}

// ---------------------------------------------------------------------------
// Flash attention (fp32 SIMT) — unchanged from R1 (932us; mma port is next)
// ---------------------------------------------------------------------------
#define QS_STRIDE 68
#define ATTN_SMEM ((128 * QS_STRIDE + 64 * QS_STRIDE + 64 * QS_STRIDE + 128 * QS_STRIDE) * (int)sizeof(float))

__global__ __launch_bounds__(256)
void attn_kernel(const float* __restrict__ Q, const float* __restrict__ K,
                 const float* __restrict__ V, float* __restrict__ O)
{
    extern __shared__ float sm[];
    float* Qs = sm;
    float* Ks = Qs + 128 * QS_STRIDE;
    float* Vs = Ks + 64 * QS_STRIDE;
    float* Ps = Vs + 64 * QS_STRIDE;

    const int tid = threadIdx.x;
    const int tx  = tid & 15;
    const int ty  = tid >> 4;
    const int bh  = blockIdx.z * H_ + blockIdx.y;
    const int q0  = blockIdx.x * 128;

    const float* qptr  = Q + ((size_t)bh * S_ + q0) * HD_;
    const float* kbase = K + (size_t)bh * S_ * HD_;
    const float* vbase = V + (size_t)bh * S_ * HD_;

#pragma unroll
    for (int i = 0; i < 8; i++) {
        int f = tid + i * 256;
        int r = f >> 4;
        int d = (f & 15) << 2;
        *(float4*)&Qs[r * QS_STRIDE + d] = *(const float4*)(qptr + (size_t)r * HD_ + d);
    }

    float m_i[8], l_i[8], acc[8][4];
#pragma unroll
    for (int i = 0; i < 8; i++) {
        m_i[i] = -1e30f; l_i[i] = 0.0f;
#pragma unroll
        for (int c = 0; c < 4; c++) acc[i][c] = 0.0f;
    }

    for (int kt = 0; kt < S_; kt += 64) {
        __syncthreads();
#pragma unroll
        for (int i = 0; i < 4; i++) {
            int f = tid + i * 256;
            int r = f >> 4;
            int d = (f & 15) << 2;
            *(float4*)&Ks[r * QS_STRIDE + d] =
                *(const float4*)(kbase + (size_t)(kt + r) * HD_ + d);
            *(float4*)&Vs[r * QS_STRIDE + d] =
                *(const float4*)(vbase + (size_t)(kt + r) * HD_ + d);
        }
        __syncthreads();

        float s[8][4];
#pragma unroll
        for (int i = 0; i < 8; i++)
#pragma unroll
            for (int c = 0; c < 4; c++) s[i][c] = 0.0f;

#pragma unroll
        for (int d0 = 0; d0 < HD_; d0 += 4) {
            float4 qv[8], kv[4];
#pragma unroll
            for (int i = 0; i < 8; i++)
                qv[i] = *(const float4*)&Qs[(ty * 8 + i) * QS_STRIDE + d0];
#pragma unroll
            for (int c = 0; c < 4; c++)
                kv[c] = *(const float4*)&Ks[(tx * 4 + c) * QS_STRIDE + d0];
#pragma unroll
            for (int i = 0; i < 8; i++)
#pragma unroll
                for (int c = 0; c < 4; c++)
                    s[i][c] += qv[i].x * kv[c].x + qv[i].y * kv[c].y +
                               qv[i].z * kv[c].z + qv[i].w * kv[c].w;
        }

#pragma unroll
        for (int i = 0; i < 8; i++) {
            float mx = -1e30f;
#pragma unroll
            for (int c = 0; c < 4; c++) { s[i][c] *= 0.125f; mx = fmaxf(mx, s[i][c]); }
#pragma unroll
            for (int off = 8; off >= 1; off >>= 1)
                mx = fmaxf(mx, __shfl_xor_sync(0xffffffffu, mx, off));
            float mnew = fmaxf(m_i[i], mx);
            float corr = __expf(m_i[i] - mnew);
            m_i[i] = mnew;
            float rs = 0.0f;
#pragma unroll
            for (int c = 0; c < 4; c++) {
                float p = __expf(s[i][c] - mnew);
                s[i][c] = p; rs += p;
            }
#pragma unroll
            for (int off = 8; off >= 1; off >>= 1)
                rs += __shfl_xor_sync(0xffffffffu, rs, off);
            l_i[i] = l_i[i] * corr + rs;
#pragma unroll
            for (int c = 0; c < 4; c++) acc[i][c] *= corr;
            *(float4*)&Ps[(ty * 8 + i) * QS_STRIDE + tx * 4] = *(float4*)&s[i][0];
        }
        __syncthreads();

#pragma unroll
        for (int j0 = 0; j0 < 64; j0 += 4) {
            float4 pv[8], vv[4];
#pragma unroll
            for (int i = 0; i < 8; i++)
                pv[i] = *(const float4*)&Ps[(ty * 8 + i) * QS_STRIDE + j0];
#pragma unroll
            for (int jj = 0; jj < 4; jj++)
                vv[jj] = *(const float4*)&Vs[(j0 + jj) * QS_STRIDE + tx * 4];
#pragma unroll
            for (int i = 0; i < 8; i++) {
                acc[i][0] += pv[i].x * vv[0].x + pv[i].y * vv[1].x + pv[i].z * vv[2].x + pv[i].w * vv[3].x;
                acc[i][1] += pv[i].x * vv[0].y + pv[i].y * vv[1].y + pv[i].z * vv[2].y + pv[i].w * vv[3].y;
                acc[i][2] += pv[i].x * vv[0].z + pv[i].y * vv[1].z + pv[i].z * vv[2].z + pv[i].w * vv[3].z;
                acc[i][3] += pv[i].x * vv[0].w + pv[i].y * vv[1].w + pv[i].z * vv[2].w + pv[i].w * vv[3].w;
            }
        }
    }

    const int b = blockIdx.z, h = blockIdx.y;
#pragma unroll
    for (int i = 0; i < 8; i++) {
        float inv = 1.0f / l_i[i];
        float4 o;
        o.x = acc[i][0] * inv; o.y = acc[i][1] * inv;
        o.z = acc[i][2] * inv; o.w = acc[i][3] * inv;
        size_t row = (size_t)b * S_ + q0 + ty * 8 + i;
        *(float4*)(O + row * D_ + h * HD_ + tx * 4) = o;
    }
}

// ---------------------------------------------------------------------------
// Launch
// ---------------------------------------------------------------------------
extern "C" void kernel_launch(void* const* d_in, const int* in_sizes, int n_in,
                              void* d_out, int out_size)
{
    const float* x  = (const float*)d_in[0];
    const float* wq = (const float*)d_in[1];
    const float* bq = (const float*)d_in[2];
    const float* wk = (const float*)d_in[3];
    const float* bk = (const float*)d_in[4];
    const float* wv = (const float*)d_in[5];
    const float* bv = (const float*)d_in[6];
    const float* wo = (const float*)d_in[7];
    const float* bo = (const float*)d_in[8];
    float* out = (float*)d_out;

    float *qp, *kp, *vp, *ap;
    __nv_bfloat16 *axp, *a2p, *wqp, *wkp, *wvp, *wop;
    cudaGetSymbolAddress((void**)&qp, g_q);
    cudaGetSymbolAddress((void**)&kp, g_k);
    cudaGetSymbolAddress((void**)&vp, g_v);
    cudaGetSymbolAddress((void**)&ap, g_attn);
    cudaGetSymbolAddress((void**)&axp, g_ax);
    cudaGetSymbolAddress((void**)&a2p, g_a2);
    cudaGetSymbolAddress((void**)&wqp, g_wq);
    cudaGetSymbolAddress((void**)&wkp, g_wk);
    cudaGetSymbolAddress((void**)&wvp, g_wv);
    cudaGetSymbolAddress((void**)&wop, g_wo);

    cudaFuncSetAttribute(attn_kernel,
                         cudaFuncAttributeMaxDynamicSharedMemorySize, ATTN_SMEM);
    cudaFuncSetAttribute(tc_gemm_kernel<0>,
                         cudaFuncAttributeMaxDynamicSharedMemorySize, GEMM_SMEM);
    cudaFuncSetAttribute(tc_gemm_kernel<1>,
                         cudaFuncAttributeMaxDynamicSharedMemorySize, GEMM_SMEM);

    split_a_kernel<<<(MTOT * D_ / 4) / 256, 256>>>(x, axp);
    split_w_kernel<<<(D_ * D_ / 4) / 256, 256>>>(wq, wqp);
    split_w_kernel<<<(D_ * D_ / 4) / 256, 256>>>(wk, wkp);
    split_w_kernel<<<(D_ * D_ / 4) / 256, 256>>>(wv, wvp);
    split_w_kernel<<<(D_ * D_ / 4) / 256, 256>>>(wo, wop);

    dim3 ggrid(D_ / 128, MTOT / 128);   // (6, 64)
    tc_gemm_kernel<1><<<ggrid, 256, GEMM_SMEM>>>(axp, wqp, bq, qp);
    tc_gemm_kernel<1><<<ggrid, 256, GEMM_SMEM>>>(axp, wkp, bk, kp);
    tc_gemm_kernel<1><<<ggrid, 256, GEMM_SMEM>>>(axp, wvp, bv, vp);

    attn_kernel<<<dim3(S_ / 128, H_, B_), 256, ATTN_SMEM>>>(qp, kp, vp, ap);

    split_a_kernel<<<(MTOT * D_ / 4) / 256, 256>>>(ap, a2p);
    tc_gemm_kernel<0><<<ggrid, 256, GEMM_SMEM>>>(a2p, wop, bo, out);
}

// round 5
// speedup vs baseline: 2.7542x; 1.8710x over previous
#include <cuda_runtime.h>
#include <cuda_bf16.h>
#include <math.h>
#include <stdint.h>

// Problem constants
#define B_   8
#define S_   1024
#define D_   768
#define H_   12
#define HD_  64
#define BH_  (B_ * H_)       // 96
#define MTOT (B_ * S_)       // 8192
#define KP_  (3 * D_)        // 2304 : [hi | hi | lo] split-K

// ---------------------------------------------------------------------------
// Scratch (device globals — no runtime allocation allowed)
// ---------------------------------------------------------------------------
__device__ float g_attn[(size_t)MTOT * D_];
__device__ __nv_bfloat16 g_ax[(size_t)MTOT * KP_];    // split(x)
__device__ __nv_bfloat16 g_a2[(size_t)MTOT * KP_];    // split(attn)
__device__ __nv_bfloat16 g_wq[(size_t)D_ * KP_];      // split(W^T) [n, k']
__device__ __nv_bfloat16 g_wk[(size_t)D_ * KP_];
__device__ __nv_bfloat16 g_wv[(size_t)D_ * KP_];
__device__ __nv_bfloat16 g_wo[(size_t)D_ * KP_];
__device__ __nv_bfloat16 g_qs[(size_t)BH_ * S_ * 128];   // Q split [bh, s, hi|lo]
__device__ __nv_bfloat16 g_ks[(size_t)BH_ * S_ * 128];   // K split
__device__ __nv_bfloat16 g_vt[(size_t)BH_ * 128 * S_];   // V^T split [bh, d(hi|lo), s]

// ---------------------------------------------------------------------------
// PTX helpers (standard sm_80+ instructions only)
// ---------------------------------------------------------------------------
__device__ __forceinline__ uint32_t smem_u32(const void* p) {
    uint32_t a;
    asm("{ .reg .u64 t; cvta.to.shared.u64 t, %1; cvt.u32.u64 %0, t; }" : "=r"(a) : "l"(p));
    return a;
}
__device__ __forceinline__ void cp_async16(uint32_t dst, const void* src) {
    asm volatile("cp.async.cg.shared.global [%0], [%1], 16;" :: "r"(dst), "l"(src) : "memory");
}
__device__ __forceinline__ void cp_commit() {
    asm volatile("cp.async.commit_group;" ::: "memory");
}
template <int N>
__device__ __forceinline__ void cp_wait() {
    asm volatile("cp.async.wait_group %0;" :: "n"(N) : "memory");
}
__device__ __forceinline__ void ldmatrix_x4(uint32_t* r, uint32_t addr) {
    asm volatile("ldmatrix.sync.aligned.m8n8.x4.shared.b16 {%0,%1,%2,%3}, [%4];"
        : "=r"(r[0]), "=r"(r[1]), "=r"(r[2]), "=r"(r[3]) : "r"(addr));
}
__device__ __forceinline__ void mma_bf16(float* c, const uint32_t* a, const uint32_t* b) {
    asm volatile(
        "mma.sync.aligned.m16n8k16.row.col.f32.bf16.bf16.f32 "
        "{%0,%1,%2,%3}, {%4,%5,%6,%7}, {%8,%9}, {%0,%1,%2,%3};"
        : "+f"(c[0]), "+f"(c[1]), "+f"(c[2]), "+f"(c[3])
        : "r"(a[0]), "r"(a[1]), "r"(a[2]), "r"(a[3]), "r"(b[0]), "r"(b[1]));
}

// SW128 swizzle for 128B rows (16B-chunk granularity)
#define SW128(off) ((off) ^ (((off) >> 3) & 0x70))

// ---------------------------------------------------------------------------
// Split kernels: fp32 -> bf16 hi/lo packed K' = [hi | hi | lo] (A)
//                                            [hi | lo | hi] (W^T)
// ---------------------------------------------------------------------------
__global__ __launch_bounds__(256) void split_a_kernel(const float* __restrict__ in,
                                                      __nv_bfloat16* __restrict__ out)
{
    int idx = blockIdx.x * blockDim.x + threadIdx.x;
    int m  = idx / (D_ / 4);
    int k4 = (idx % (D_ / 4)) * 4;
    float4 x = *(const float4*)(in + (size_t)m * D_ + k4);
    float xs[4] = {x.x, x.y, x.z, x.w};
    __nv_bfloat16 hi[4], lo[4];
#pragma unroll
    for (int i = 0; i < 4; i++) {
        hi[i] = __float2bfloat16(xs[i]);
        lo[i] = __float2bfloat16(xs[i] - __bfloat162float(hi[i]));
    }
    uint2 hp, lp;
    ((__nv_bfloat162*)&hp)[0] = __nv_bfloat162(hi[0], hi[1]);
    ((__nv_bfloat162*)&hp)[1] = __nv_bfloat162(hi[2], hi[3]);
    ((__nv_bfloat162*)&lp)[0] = __nv_bfloat162(lo[0], lo[1]);
    ((__nv_bfloat162*)&lp)[1] = __nv_bfloat162(lo[2], lo[3]);
    __nv_bfloat16* row = out + (size_t)m * KP_;
    *(uint2*)(row + k4)            = hp;
    *(uint2*)(row + D_ + k4)       = hp;
    *(uint2*)(row + 2 * D_ + k4)   = lp;
}

__global__ __launch_bounds__(256) void split_w_kernel(const float* __restrict__ w,
                                                      __nv_bfloat16* __restrict__ out)
{
    int idx = blockIdx.x * blockDim.x + threadIdx.x;
    int n  = idx / (D_ / 4);
    int k4 = (idx % (D_ / 4)) * 4;
    __nv_bfloat16 hi[4], lo[4];
#pragma unroll
    for (int i = 0; i < 4; i++) {
        float x = w[(size_t)(k4 + i) * D_ + n];
        hi[i] = __float2bfloat16(x);
        lo[i] = __float2bfloat16(x - __bfloat162float(hi[i]));
    }
    uint2 hp, lp;
    ((__nv_bfloat162*)&hp)[0] = __nv_bfloat162(hi[0], hi[1]);
    ((__nv_bfloat162*)&hp)[1] = __nv_bfloat162(hi[2], hi[3]);
    ((__nv_bfloat162*)&lp)[0] = __nv_bfloat162(lo[0], lo[1]);
    ((__nv_bfloat162*)&lp)[1] = __nv_bfloat162(lo[2], lo[3]);
    __nv_bfloat16* row = out + (size_t)n * KP_;
    *(uint2*)(row + k4)          = hp;
    *(uint2*)(row + D_ + k4)     = lp;
    *(uint2*)(row + 2 * D_ + k4) = hp;
}

// ---------------------------------------------------------------------------
// mma.sync GEMM: C[M, N=768] = A'[M, KP_] @ W'^T + bias.
// MODE 0: fp32 row-major [M,768] (output projection)
// MODE 1: bf16 hi/lo split rows [bh, s, 128]  (Q, K)
// MODE 2: bf16 hi/lo split transposed [bh, d(hi|lo), s]  (V)
// ---------------------------------------------------------------------------
#define BK_        64
#define NT_        (KP_ / BK_)            // 36
#define TILE_B     (128 * 128)            // 16KB
#define GEMM_SMEM  (4 * TILE_B)           // 64KB

template <int MODE>
__global__ __launch_bounds__(256)
void tc_gemm_kernel(const __nv_bfloat16* __restrict__ A,
                    const __nv_bfloat16* __restrict__ W,
                    const float* __restrict__ bias,
                    float* __restrict__ outf, __nv_bfloat16* __restrict__ outb)
{
    extern __shared__ char smem_raw[];
    const uint32_t sbase = smem_u32(smem_raw);
    const int tid  = threadIdx.x;
    const int wid  = tid >> 5;
    const int lane = tid & 31;
    const int wm   = (wid & 1) * 64;
    const int wn   = (wid >> 1) * 32;
    const int m0   = blockIdx.y * 128;
    const int n0   = blockIdx.x * 128;

    const int lr = tid >> 1;
    const int lc = (tid & 1) * 4;

    float acc[4][4][4];
#pragma unroll
    for (int i = 0; i < 4; i++)
#pragma unroll
        for (int j = 0; j < 4; j++)
#pragma unroll
            for (int e = 0; e < 4; e++) acc[i][j][e] = 0.0f;

    auto load_stage = [&](int it, int s) {
        const uint32_t sA = sbase + s * 2 * TILE_B;
        const uint32_t sB = sA + TILE_B;
        const int k0 = it * BK_;
        const __nv_bfloat16* Ag = A + (size_t)(m0 + lr) * KP_ + k0 + lc * 8;
        const __nv_bfloat16* Wg = W + (size_t)(n0 + lr) * KP_ + k0 + lc * 8;
#pragma unroll
        for (int c = 0; c < 4; c++) {
            uint32_t off = SW128((uint32_t)(lr * 128 + (lc + c) * 16));
            cp_async16(sA + off, Ag + c * 8);
            cp_async16(sB + off, Wg + c * 8);
        }
    };

    load_stage(0, 0);
    cp_commit();

    const int a_row = wm + (lane & 15);
    const int a_cb  = (lane >> 4) << 4;
    const int b_row = wn + (lane & 7) + ((lane >> 4) << 3);
    const int b_cb  = ((lane >> 3) & 1) << 4;

    for (int it = 0; it < NT_; it++) {
        const int s = it & 1;
        if (it + 1 < NT_) {
            load_stage(it + 1, s ^ 1);
            cp_commit();
            cp_wait<1>();
        } else {
            cp_wait<0>();
        }
        __syncthreads();

        const uint32_t sA = sbase + s * 2 * TILE_B;
        const uint32_t sB = sA + TILE_B;

#pragma unroll
        for (int ks = 0; ks < BK_ / 16; ks++) {
            uint32_t af[4][4], bf[2][4];
#pragma unroll
            for (int mt = 0; mt < 4; mt++) {
                uint32_t off = SW128((uint32_t)((a_row + mt * 16) * 128 + ks * 32 + a_cb));
                ldmatrix_x4(af[mt], sA + off);
            }
#pragma unroll
            for (int nt2 = 0; nt2 < 2; nt2++) {
                uint32_t off = SW128((uint32_t)((b_row + nt2 * 16) * 128 + ks * 32 + b_cb));
                ldmatrix_x4(bf[nt2], sB + off);
            }
#pragma unroll
            for (int mt = 0; mt < 4; mt++)
#pragma unroll
                for (int nt = 0; nt < 4; nt++)
                    mma_bf16(acc[mt][nt], af[mt], &bf[nt >> 1][(nt & 1) * 2]);
        }
        __syncthreads();
    }

#pragma unroll
    for (int mt = 0; mt < 4; mt++) {
#pragma unroll
        for (int nt = 0; nt < 4; nt++) {
            int m = m0 + wm + mt * 16 + (lane >> 2);
            int n = n0 + wn + nt * 8 + (lane & 3) * 2;
            float2 bv = *(const float2*)(bias + n);
            float2 v0 = {acc[mt][nt][0] + bv.x, acc[mt][nt][1] + bv.y};
            float2 v1 = {acc[mt][nt][2] + bv.x, acc[mt][nt][3] + bv.y};
            if (MODE == 0) {
                *(float2*)(outf + (size_t)m * D_ + n) = v0;
                *(float2*)(outf + (size_t)(m + 8) * D_ + n) = v1;
            } else {
                int b = m >> 10, sq = m & 1023;
                int h = n >> 6, d = n & 63;
                int bh = b * H_ + h;
                if (MODE == 1) {
                    // [bh, s, 128] rows: hi at d, lo at d+64
                    size_t base = ((size_t)bh * S_ + sq) * 128 + d;
                    __nv_bfloat162 h0 = __float22bfloat162_rn(v0);
                    float2 hf0 = __bfloat1622float2(h0);
                    __nv_bfloat162 l0 = __float22bfloat162_rn(
                        make_float2(v0.x - hf0.x, v0.y - hf0.y));
                    __nv_bfloat162 h1 = __float22bfloat162_rn(v1);
                    float2 hf1 = __bfloat1622float2(h1);
                    __nv_bfloat162 l1 = __float22bfloat162_rn(
                        make_float2(v1.x - hf1.x, v1.y - hf1.y));
                    *(__nv_bfloat162*)(outb + base)            = h0;
                    *(__nv_bfloat162*)(outb + base + 64)       = l0;
                    *(__nv_bfloat162*)(outb + base + 8 * 128)      = h1;
                    *(__nv_bfloat162*)(outb + base + 8 * 128 + 64) = l1;
                } else {
                    // V^T [bh, d(hi|lo), s]
                    size_t r0 = ((size_t)bh * 128 + d) * S_;
                    size_t r1 = r0 + S_;                 // d+1
                    size_t lofs = (size_t)64 * S_;       // lo plane
                    __nv_bfloat16 h00 = __float2bfloat16(v0.x);
                    __nv_bfloat16 h01 = __float2bfloat16(v0.y);
                    __nv_bfloat16 h10 = __float2bfloat16(v1.x);
                    __nv_bfloat16 h11 = __float2bfloat16(v1.y);
                    outb[r0 + sq] = h00;
                    outb[r1 + sq] = h01;
                    outb[r0 + sq + 8] = h10;
                    outb[r1 + sq + 8] = h11;
                    outb[r0 + lofs + sq] = __float2bfloat16(v0.x - __bfloat162float(h00));
                    outb[r1 + lofs + sq] = __float2bfloat16(v0.y - __bfloat162float(h01));
                    outb[r0 + lofs + sq + 8] = __float2bfloat16(v1.x - __bfloat162float(h10));
                    outb[r1 + lofs + sq + 8] = __float2bfloat16(v1.y - __bfloat162float(h11));
                }
            }
        }
    }
}

// ---------------------------------------------------------------------------
// Tensor-core flash attention.
// One CTA per (b, h, 128-query tile). 8 warps x 16 q-rows, full 64-kv width.
// S = [Qhi|Qlo|Qhi] @ [Khi|Khi|Klo]^T ; O = Phi@Vhi + Plo@Vhi + Phi@Vlo.
// smem: Qhi/Qlo planes (16KB each) + 2 stages x (Khi,Klo,Vhi,Vlo 8KB each).
// ---------------------------------------------------------------------------
#define AQ_HI   0
#define AQ_LO   16384
#define AST(s)  (32768 + (s) * 32768)
#define ATTN_SMEM 98304
#define SC_LOG2E 0.18033688f    // 0.125 * log2(e)

__global__ __launch_bounds__(256)
void attn_mma_kernel(const __nv_bfloat16* __restrict__ Q,
                     const __nv_bfloat16* __restrict__ K,
                     const __nv_bfloat16* __restrict__ Vt,
                     float* __restrict__ O)
{
    extern __shared__ char smem_raw[];
    const uint32_t sb = smem_u32(smem_raw);
    const int tid  = threadIdx.x;
    const int wid  = tid >> 5;
    const int lane = tid & 31;
    const int bh   = blockIdx.z * H_ + blockIdx.y;
    const int q0   = blockIdx.x * 128;

    // ---- Q load: 8 chunks per thread (4 hi + 4 lo) ----
    {
        int r  = tid >> 1;
        int lc = (tid & 1) * 4;
        const __nv_bfloat16* qrow = Q + ((size_t)bh * S_ + q0 + r) * 128;
#pragma unroll
        for (int c = 0; c < 4; c++) {
            uint32_t off = SW128((uint32_t)(r * 128 + (lc + c) * 16));
            cp_async16(sb + AQ_HI + off, qrow + (lc + c) * 8);
            cp_async16(sb + AQ_LO + off, qrow + 64 + (lc + c) * 8);
        }
    }

    // KV stage loader: 8 chunks per thread (2 per plane)
    auto load_kv = [&](int kt, int s) {
        int r  = tid >> 2;            // 0..63
        int c2 = (tid & 3) * 2;
        const __nv_bfloat16* krow = K + ((size_t)bh * S_ + kt + r) * 128;
        const __nv_bfloat16* vhr  = Vt + ((size_t)bh * 128 + r) * S_ + kt;
        const __nv_bfloat16* vlr  = Vt + ((size_t)bh * 128 + 64 + r) * S_ + kt;
        const uint32_t st = sb + AST(s);
#pragma unroll
        for (int cc = 0; cc < 2; cc++) {
            int c = c2 + cc;
            uint32_t off = SW128((uint32_t)(r * 128 + c * 16));
            cp_async16(st + off,         krow + c * 8);        // Khi
            cp_async16(st + 8192 + off,  krow + 64 + c * 8);   // Klo
            cp_async16(st + 16384 + off, vhr + c * 8);         // Vhi
            cp_async16(st + 24576 + off, vlr + c * 8);         // Vlo
        }
    };

    load_kv(0, 0);
    cp_commit();

    // fragment address components
    const int a_row = wid * 16 + (lane & 15);
    const int a_cb  = (lane >> 4) << 4;
    const int b_row = (lane & 7) + ((lane >> 4) << 3);
    const int b_cb  = ((lane >> 3) & 1) << 4;

    float m0 = -1e30f, m1 = -1e30f, l0 = 0.0f, l1 = 0.0f;
    float oacc[8][4];
#pragma unroll
    for (int j = 0; j < 8; j++)
#pragma unroll
        for (int e = 0; e < 4; e++) oacc[j][e] = 0.0f;

    for (int it = 0; it < S_ / 64; it++) {
        const int s = it & 1;
        if (it + 1 < S_ / 64) {
            load_kv((it + 1) * 64, s ^ 1);
            cp_commit();
            cp_wait<1>();
        } else {
            cp_wait<0>();
        }
        __syncthreads();

        const uint32_t stK_hi = sb + AST(s);
        const uint32_t stK_lo = stK_hi + 8192;
        const uint32_t stV_hi = stK_hi + 16384;
        const uint32_t stV_lo = stK_hi + 24576;

        // ---- S = Qhi.Khi + Qlo.Khi + Qhi.Klo ----
        float sacc[8][4];
#pragma unroll
        for (int j = 0; j < 8; j++)
#pragma unroll
            for (int e = 0; e < 4; e++) sacc[j][e] = 0.0f;

#pragma unroll
        for (int ks = 0; ks < 4; ks++) {
            uint32_t bk[4][4], af[4];
#pragma unroll
            for (int nt2 = 0; nt2 < 4; nt2++) {
                uint32_t off = SW128((uint32_t)((b_row + nt2 * 16) * 128 + ks * 32 + b_cb));
                ldmatrix_x4(bk[nt2], stK_hi + off);
            }
            uint32_t aoff = SW128((uint32_t)(a_row * 128 + ks * 32 + a_cb));
            ldmatrix_x4(af, sb + AQ_HI + aoff);
#pragma unroll
            for (int j = 0; j < 8; j++)
                mma_bf16(sacc[j], af, &bk[j >> 1][(j & 1) * 2]);
            ldmatrix_x4(af, sb + AQ_LO + aoff);
#pragma unroll
            for (int j = 0; j < 8; j++)
                mma_bf16(sacc[j], af, &bk[j >> 1][(j & 1) * 2]);
        }
#pragma unroll
        for (int ks = 0; ks < 4; ks++) {
            uint32_t bk[4][4], af[4];
#pragma unroll
            for (int nt2 = 0; nt2 < 4; nt2++) {
                uint32_t off = SW128((uint32_t)((b_row + nt2 * 16) * 128 + ks * 32 + b_cb));
                ldmatrix_x4(bk[nt2], stK_lo + off);
            }
            uint32_t aoff = SW128((uint32_t)(a_row * 128 + ks * 32 + a_cb));
            ldmatrix_x4(af, sb + AQ_HI + aoff);
#pragma unroll
            for (int j = 0; j < 8; j++)
                mma_bf16(sacc[j], af, &bk[j >> 1][(j & 1) * 2]);
        }

        // ---- online softmax (exp2 domain, scale folded) ----
        float mx0 = -1e30f, mx1 = -1e30f;
#pragma unroll
        for (int j = 0; j < 8; j++) {
            mx0 = fmaxf(mx0, fmaxf(sacc[j][0], sacc[j][1]));
            mx1 = fmaxf(mx1, fmaxf(sacc[j][2], sacc[j][3]));
        }
        mx0 = fmaxf(mx0, __shfl_xor_sync(0xffffffffu, mx0, 1));
        mx0 = fmaxf(mx0, __shfl_xor_sync(0xffffffffu, mx0, 2));
        mx1 = fmaxf(mx1, __shfl_xor_sync(0xffffffffu, mx1, 1));
        mx1 = fmaxf(mx1, __shfl_xor_sync(0xffffffffu, mx1, 2));
        float mn0 = fmaxf(m0, mx0), mn1 = fmaxf(m1, mx1);
        float corr0 = exp2f((m0 - mn0) * SC_LOG2E);
        float corr1 = exp2f((m1 - mn1) * SC_LOG2E);
        m0 = mn0; m1 = mn1;

        uint32_t phi[8][2], plo[8][2];
        float rs0 = 0.0f, rs1 = 0.0f;
#pragma unroll
        for (int j = 0; j < 8; j++) {
            float p0 = exp2f((sacc[j][0] - m0) * SC_LOG2E);
            float p1 = exp2f((sacc[j][1] - m0) * SC_LOG2E);
            float p2 = exp2f((sacc[j][2] - m1) * SC_LOG2E);
            float p3 = exp2f((sacc[j][3] - m1) * SC_LOG2E);
            rs0 += p0 + p1;
            rs1 += p2 + p3;
            __nv_bfloat162 h01 = __float22bfloat162_rn(make_float2(p0, p1));
            float2 hf = __bfloat1622float2(h01);
            __nv_bfloat162 l01 = __float22bfloat162_rn(make_float2(p0 - hf.x, p1 - hf.y));
            phi[j][0] = *(uint32_t*)&h01;
            plo[j][0] = *(uint32_t*)&l01;
            __nv_bfloat162 h23 = __float22bfloat162_rn(make_float2(p2, p3));
            float2 hf2 = __bfloat1622float2(h23);
            __nv_bfloat162 l23 = __float22bfloat162_rn(make_float2(p2 - hf2.x, p3 - hf2.y));
            phi[j][1] = *(uint32_t*)&h23;
            plo[j][1] = *(uint32_t*)&l23;
        }
        rs0 += __shfl_xor_sync(0xffffffffu, rs0, 1);
        rs0 += __shfl_xor_sync(0xffffffffu, rs0, 2);
        rs1 += __shfl_xor_sync(0xffffffffu, rs1, 1);
        rs1 += __shfl_xor_sync(0xffffffffu, rs1, 2);
        l0 = l0 * corr0 + rs0;
        l1 = l1 * corr1 + rs1;
#pragma unroll
        for (int j = 0; j < 8; j++) {
            oacc[j][0] *= corr0; oacc[j][1] *= corr0;
            oacc[j][2] *= corr1; oacc[j][3] *= corr1;
        }

        // ---- O += Phi.Vhi + Plo.Vhi + Phi.Vlo ----
#pragma unroll
        for (int kc = 0; kc < 4; kc++) {
            uint32_t bv[4][4];
#pragma unroll
            for (int nt2 = 0; nt2 < 4; nt2++) {
                uint32_t off = SW128((uint32_t)((b_row + nt2 * 16) * 128 + kc * 32 + b_cb));
                ldmatrix_x4(bv[nt2], stV_hi + off);
            }
            uint32_t ah[4] = {phi[2 * kc][0], phi[2 * kc][1], phi[2 * kc + 1][0], phi[2 * kc + 1][1]};
            uint32_t al[4] = {plo[2 * kc][0], plo[2 * kc][1], plo[2 * kc + 1][0], plo[2 * kc + 1][1]};
#pragma unroll
            for (int j = 0; j < 8; j++) {
                mma_bf16(oacc[j], ah, &bv[j >> 1][(j & 1) * 2]);
                mma_bf16(oacc[j], al, &bv[j >> 1][(j & 1) * 2]);
            }
        }
#pragma unroll
        for (int kc = 0; kc < 4; kc++) {
            uint32_t bv[4][4];
#pragma unroll
            for (int nt2 = 0; nt2 < 4; nt2++) {
                uint32_t off = SW128((uint32_t)((b_row + nt2 * 16) * 128 + kc * 32 + b_cb));
                ldmatrix_x4(bv[nt2], stV_lo + off);
            }
            uint32_t ah[4] = {phi[2 * kc][0], phi[2 * kc][1], phi[2 * kc + 1][0], phi[2 * kc + 1][1]};
#pragma unroll
            for (int j = 0; j < 8; j++)
                mma_bf16(oacc[j], ah, &bv[j >> 1][(j & 1) * 2]);
        }
        __syncthreads();
    }

    // ---- epilogue: write g_attn [b*S+q, h*64+d] ----
    const int b = blockIdx.z, h = blockIdx.y;
    const float inv0 = 1.0f / l0, inv1 = 1.0f / l1;
    const int qr = q0 + wid * 16 + (lane >> 2);
    const int nc = h * HD_ + (lane & 3) * 2;
#pragma unroll
    for (int j = 0; j < 8; j++) {
        float2 v0 = {oacc[j][0] * inv0, oacc[j][1] * inv0};
        float2 v1 = {oacc[j][2] * inv1, oacc[j][3] * inv1};
        size_t r0 = (size_t)(b * S_ + qr) * D_ + nc + j * 8;
        *(float2*)(O + r0) = v0;
        *(float2*)(O + r0 + 8 * D_) = v1;
    }
}

// ---------------------------------------------------------------------------
// Launch
// ---------------------------------------------------------------------------
extern "C" void kernel_launch(void* const* d_in, const int* in_sizes, int n_in,
                              void* d_out, int out_size)
{
    const float* x  = (const float*)d_in[0];
    const float* wq = (const float*)d_in[1];
    const float* bq = (const float*)d_in[2];
    const float* wk = (const float*)d_in[3];
    const float* bk = (const float*)d_in[4];
    const float* wv = (const float*)d_in[5];
    const float* bv = (const float*)d_in[6];
    const float* wo = (const float*)d_in[7];
    const float* bo = (const float*)d_in[8];
    float* out = (float*)d_out;

    float* ap;
    __nv_bfloat16 *axp, *a2p, *wqp, *wkp, *wvp, *wop, *qsp, *ksp, *vtp;
    cudaGetSymbolAddress((void**)&ap, g_attn);
    cudaGetSymbolAddress((void**)&axp, g_ax);
    cudaGetSymbolAddress((void**)&a2p, g_a2);
    cudaGetSymbolAddress((void**)&wqp, g_wq);
    cudaGetSymbolAddress((void**)&wkp, g_wk);
    cudaGetSymbolAddress((void**)&wvp, g_wv);
    cudaGetSymbolAddress((void**)&wop, g_wo);
    cudaGetSymbolAddress((void**)&qsp, g_qs);
    cudaGetSymbolAddress((void**)&ksp, g_ks);
    cudaGetSymbolAddress((void**)&vtp, g_vt);

    cudaFuncSetAttribute(attn_mma_kernel,
                         cudaFuncAttributeMaxDynamicSharedMemorySize, ATTN_SMEM);
    cudaFuncSetAttribute(tc_gemm_kernel<0>,
                         cudaFuncAttributeMaxDynamicSharedMemorySize, GEMM_SMEM);
    cudaFuncSetAttribute(tc_gemm_kernel<1>,
                         cudaFuncAttributeMaxDynamicSharedMemorySize, GEMM_SMEM);
    cudaFuncSetAttribute(tc_gemm_kernel<2>,
                         cudaFuncAttributeMaxDynamicSharedMemorySize, GEMM_SMEM);

    split_a_kernel<<<(MTOT * D_ / 4) / 256, 256>>>(x, axp);
    split_w_kernel<<<(D_ * D_ / 4) / 256, 256>>>(wq, wqp);
    split_w_kernel<<<(D_ * D_ / 4) / 256, 256>>>(wk, wkp);
    split_w_kernel<<<(D_ * D_ / 4) / 256, 256>>>(wv, wvp);
    split_w_kernel<<<(D_ * D_ / 4) / 256, 256>>>(wo, wop);

    dim3 ggrid(D_ / 128, MTOT / 128);   // (6, 64)
    tc_gemm_kernel<1><<<ggrid, 256, GEMM_SMEM>>>(axp, wqp, bq, nullptr, qsp);
    tc_gemm_kernel<1><<<ggrid, 256, GEMM_SMEM>>>(axp, wkp, bk, nullptr, ksp);
    tc_gemm_kernel<2><<<ggrid, 256, GEMM_SMEM>>>(axp, wvp, bv, nullptr, vtp);

    attn_mma_kernel<<<dim3(S_ / 128, H_, B_), 256, ATTN_SMEM>>>(qsp, ksp, vtp, ap);

    split_a_kernel<<<(MTOT * D_ / 4) / 256, 256>>>(ap, a2p);
    tc_gemm_kernel<0><<<ggrid, 256, GEMM_SMEM>>>(a2p, wop, bo, out, nullptr);
}

// round 6
// speedup vs baseline: 3.3412x; 1.2131x over previous
#include <cuda_runtime.h>
#include <cuda_bf16.h>
#include <cuda_fp16.h>
#include <math.h>
#include <stdint.h>

// Problem constants
#define B_   8
#define S_   1024
#define D_   768
#define H_   12
#define HD_  64
#define BH_  (B_ * H_)       // 96
#define MTOT (B_ * S_)       // 8192
#define KP_  (3 * D_)        // 2304 : [hi | hi | lo] split-K

// ---------------------------------------------------------------------------
// Scratch (device globals — no runtime allocation allowed)
// ---------------------------------------------------------------------------
__device__ __nv_bfloat16 g_ax[(size_t)MTOT * KP_];    // split(x)
__device__ __nv_bfloat16 g_a2[(size_t)MTOT * KP_];    // split(attn out), written by attn
__device__ __nv_bfloat16 g_wq[(size_t)D_ * KP_];      // split(W^T) [n, k']
__device__ __nv_bfloat16 g_wk[(size_t)D_ * KP_];
__device__ __nv_bfloat16 g_wv[(size_t)D_ * KP_];
__device__ __nv_bfloat16 g_wo[(size_t)D_ * KP_];
__device__ __half g_qh[(size_t)BH_ * S_ * HD_];       // Q fp16 [bh, s, d]
__device__ __half g_kh[(size_t)BH_ * S_ * HD_];       // K fp16 [bh, s, d]
__device__ __half g_vt[(size_t)BH_ * HD_ * S_];       // V^T fp16 [bh, d, s]

// ---------------------------------------------------------------------------
// PTX helpers (standard sm_80+ instructions only)
// ---------------------------------------------------------------------------
__device__ __forceinline__ uint32_t smem_u32(const void* p) {
    uint32_t a;
    asm("{ .reg .u64 t; cvta.to.shared.u64 t, %1; cvt.u32.u64 %0, t; }" : "=r"(a) : "l"(p));
    return a;
}
__device__ __forceinline__ void cp_async16(uint32_t dst, const void* src) {
    asm volatile("cp.async.cg.shared.global [%0], [%1], 16;" :: "r"(dst), "l"(src) : "memory");
}
__device__ __forceinline__ void cp_commit() {
    asm volatile("cp.async.commit_group;" ::: "memory");
}
template <int N>
__device__ __forceinline__ void cp_wait() {
    asm volatile("cp.async.wait_group %0;" :: "n"(N) : "memory");
}
__device__ __forceinline__ void ldmatrix_x4(uint32_t* r, uint32_t addr) {
    asm volatile("ldmatrix.sync.aligned.m8n8.x4.shared.b16 {%0,%1,%2,%3}, [%4];"
        : "=r"(r[0]), "=r"(r[1]), "=r"(r[2]), "=r"(r[3]) : "r"(addr));
}
__device__ __forceinline__ void mma_bf16(float* c, const uint32_t* a, const uint32_t* b) {
    asm volatile(
        "mma.sync.aligned.m16n8k16.row.col.f32.bf16.bf16.f32 "
        "{%0,%1,%2,%3}, {%4,%5,%6,%7}, {%8,%9}, {%0,%1,%2,%3};"
        : "+f"(c[0]), "+f"(c[1]), "+f"(c[2]), "+f"(c[3])
        : "r"(a[0]), "r"(a[1]), "r"(a[2]), "r"(a[3]), "r"(b[0]), "r"(b[1]));
}
__device__ __forceinline__ void mma_f16(float* c, const uint32_t* a, const uint32_t* b) {
    asm volatile(
        "mma.sync.aligned.m16n8k16.row.col.f32.f16.f16.f32 "
        "{%0,%1,%2,%3}, {%4,%5,%6,%7}, {%8,%9}, {%0,%1,%2,%3};"
        : "+f"(c[0]), "+f"(c[1]), "+f"(c[2]), "+f"(c[3])
        : "r"(a[0]), "r"(a[1]), "r"(a[2]), "r"(a[3]), "r"(b[0]), "r"(b[1]));
}

// SW128 swizzle for 128B rows (16B-chunk granularity)
#define SW128(off) ((off) ^ (((off) >> 3) & 0x70))

// ---------------------------------------------------------------------------
// Split kernels: fp32 -> bf16 hi/lo packed K' = [hi | hi | lo] (A)
//                                            [hi | lo | hi] (W^T)
// ---------------------------------------------------------------------------
__global__ __launch_bounds__(256) void split_a_kernel(const float* __restrict__ in,
                                                      __nv_bfloat16* __restrict__ out)
{
    int idx = blockIdx.x * blockDim.x + threadIdx.x;
    int m  = idx / (D_ / 4);
    int k4 = (idx % (D_ / 4)) * 4;
    float4 x = *(const float4*)(in + (size_t)m * D_ + k4);
    float xs[4] = {x.x, x.y, x.z, x.w};
    __nv_bfloat16 hi[4], lo[4];
#pragma unroll
    for (int i = 0; i < 4; i++) {
        hi[i] = __float2bfloat16(xs[i]);
        lo[i] = __float2bfloat16(xs[i] - __bfloat162float(hi[i]));
    }
    uint2 hp, lp;
    ((__nv_bfloat162*)&hp)[0] = __nv_bfloat162(hi[0], hi[1]);
    ((__nv_bfloat162*)&hp)[1] = __nv_bfloat162(hi[2], hi[3]);
    ((__nv_bfloat162*)&lp)[0] = __nv_bfloat162(lo[0], lo[1]);
    ((__nv_bfloat162*)&lp)[1] = __nv_bfloat162(lo[2], lo[3]);
    __nv_bfloat16* row = out + (size_t)m * KP_;
    *(uint2*)(row + k4)            = hp;
    *(uint2*)(row + D_ + k4)       = hp;
    *(uint2*)(row + 2 * D_ + k4)   = lp;
}

__global__ __launch_bounds__(256) void split_w_kernel(const float* __restrict__ w,
                                                      __nv_bfloat16* __restrict__ out)
{
    int idx = blockIdx.x * blockDim.x + threadIdx.x;
    int n  = idx / (D_ / 4);
    int k4 = (idx % (D_ / 4)) * 4;
    __nv_bfloat16 hi[4], lo[4];
#pragma unroll
    for (int i = 0; i < 4; i++) {
        float x = w[(size_t)(k4 + i) * D_ + n];
        hi[i] = __float2bfloat16(x);
        lo[i] = __float2bfloat16(x - __bfloat162float(hi[i]));
    }
    uint2 hp, lp;
    ((__nv_bfloat162*)&hp)[0] = __nv_bfloat162(hi[0], hi[1]);
    ((__nv_bfloat162*)&hp)[1] = __nv_bfloat162(hi[2], hi[3]);
    ((__nv_bfloat162*)&lp)[0] = __nv_bfloat162(lo[0], lo[1]);
    ((__nv_bfloat162*)&lp)[1] = __nv_bfloat162(lo[2], lo[3]);
    __nv_bfloat16* row = out + (size_t)n * KP_;
    *(uint2*)(row + k4)          = hp;
    *(uint2*)(row + D_ + k4)     = lp;
    *(uint2*)(row + 2 * D_ + k4) = hp;
}

// ---------------------------------------------------------------------------
// mma.sync bf16x3 GEMM: C[M, N=768] = A'[M, KP_] @ W'^T + bias.
// MODE 0: fp32 row-major [M,768] (output projection, -> d_out)
// MODE 1: fp16 [bh, s, 64]  (Q, K)
// MODE 2: fp16 V^T [bh, d, s]  (V)
// ---------------------------------------------------------------------------
#define BK_        64
#define NT_        (KP_ / BK_)            // 36
#define TILE_B     (128 * 128)            // 16KB
#define GEMM_SMEM  (4 * TILE_B)           // 64KB

template <int MODE>
__global__ __launch_bounds__(256)
void tc_gemm_kernel(const __nv_bfloat16* __restrict__ A,
                    const __nv_bfloat16* __restrict__ W,
                    const float* __restrict__ bias,
                    float* __restrict__ outf, __half* __restrict__ outh)
{
    extern __shared__ char smem_raw[];
    const uint32_t sbase = smem_u32(smem_raw);
    const int tid  = threadIdx.x;
    const int wid  = tid >> 5;
    const int lane = tid & 31;
    const int wm   = (wid & 1) * 64;
    const int wn   = (wid >> 1) * 32;
    const int m0   = blockIdx.y * 128;
    const int n0   = blockIdx.x * 128;

    const int lr = tid >> 1;
    const int lc = (tid & 1) * 4;

    float acc[4][4][4];
#pragma unroll
    for (int i = 0; i < 4; i++)
#pragma unroll
        for (int j = 0; j < 4; j++)
#pragma unroll
            for (int e = 0; e < 4; e++) acc[i][j][e] = 0.0f;

    auto load_stage = [&](int it, int s) {
        const uint32_t sA = sbase + s * 2 * TILE_B;
        const uint32_t sB = sA + TILE_B;
        const int k0 = it * BK_;
        const __nv_bfloat16* Ag = A + (size_t)(m0 + lr) * KP_ + k0 + lc * 8;
        const __nv_bfloat16* Wg = W + (size_t)(n0 + lr) * KP_ + k0 + lc * 8;
#pragma unroll
        for (int c = 0; c < 4; c++) {
            uint32_t off = SW128((uint32_t)(lr * 128 + (lc + c) * 16));
            cp_async16(sA + off, Ag + c * 8);
            cp_async16(sB + off, Wg + c * 8);
        }
    };

    load_stage(0, 0);
    cp_commit();

    const int a_row = wm + (lane & 15);
    const int a_cb  = (lane >> 4) << 4;
    const int b_row = wn + (lane & 7) + ((lane >> 4) << 3);
    const int b_cb  = ((lane >> 3) & 1) << 4;

    for (int it = 0; it < NT_; it++) {
        const int s = it & 1;
        if (it + 1 < NT_) {
            load_stage(it + 1, s ^ 1);
            cp_commit();
            cp_wait<1>();
        } else {
            cp_wait<0>();
        }
        __syncthreads();

        const uint32_t sA = sbase + s * 2 * TILE_B;
        const uint32_t sB = sA + TILE_B;

#pragma unroll
        for (int ks = 0; ks < BK_ / 16; ks++) {
            uint32_t af[4][4], bf[2][4];
#pragma unroll
            for (int mt = 0; mt < 4; mt++) {
                uint32_t off = SW128((uint32_t)((a_row + mt * 16) * 128 + ks * 32 + a_cb));
                ldmatrix_x4(af[mt], sA + off);
            }
#pragma unroll
            for (int nt2 = 0; nt2 < 2; nt2++) {
                uint32_t off = SW128((uint32_t)((b_row + nt2 * 16) * 128 + ks * 32 + b_cb));
                ldmatrix_x4(bf[nt2], sB + off);
            }
#pragma unroll
            for (int mt = 0; mt < 4; mt++)
#pragma unroll
                for (int nt = 0; nt < 4; nt++)
                    mma_bf16(acc[mt][nt], af[mt], &bf[nt >> 1][(nt & 1) * 2]);
        }
        __syncthreads();
    }

#pragma unroll
    for (int mt = 0; mt < 4; mt++) {
#pragma unroll
        for (int nt = 0; nt < 4; nt++) {
            int m = m0 + wm + mt * 16 + (lane >> 2);
            int n = n0 + wn + nt * 8 + (lane & 3) * 2;
            float2 bv = *(const float2*)(bias + n);
            float2 v0 = {acc[mt][nt][0] + bv.x, acc[mt][nt][1] + bv.y};
            float2 v1 = {acc[mt][nt][2] + bv.x, acc[mt][nt][3] + bv.y};
            if (MODE == 0) {
                *(float2*)(outf + (size_t)m * D_ + n) = v0;
                *(float2*)(outf + (size_t)(m + 8) * D_ + n) = v1;
            } else {
                int b = m >> 10, sq = m & 1023;
                int h = n >> 6, d = n & 63;
                int bh = b * H_ + h;
                if (MODE == 1) {
                    size_t base = ((size_t)bh * S_ + sq) * HD_ + d;
                    *(__half2*)(outh + base)            = __float22half2_rn(v0);
                    *(__half2*)(outh + base + 8 * HD_)  = __float22half2_rn(v1);
                } else {
                    size_t r0 = ((size_t)bh * HD_ + d) * S_ + sq;
                    outh[r0]          = __float2half_rn(v0.x);
                    outh[r0 + S_]     = __float2half_rn(v0.y);
                    outh[r0 + 8]      = __float2half_rn(v1.x);
                    outh[r0 + S_ + 8] = __float2half_rn(v1.y);
                }
            }
        }
    }
}

// ---------------------------------------------------------------------------
// Tensor-core flash attention, fp16 operands.
// S = Q16 @ K16^T (1 pass). O = Phi@V16 + Plo@V16 (P fp16 hi/lo, 2 passes).
// smem: Q plane 16KB + 2 stages x (K 8KB + Vt 8KB) = 48KB.
// Epilogue writes bf16 [hi|hi|lo] rows of g_a2 directly (O-proj A operand).
// ---------------------------------------------------------------------------
#define AST(s)  (16384 + (s) * 16384)
#define ATTN_SMEM 49152
#define SC_LOG2E 0.18033688f    // 0.125 * log2(e)

__global__ __launch_bounds__(256)
void attn_mma_kernel(const __half* __restrict__ Q,
                     const __half* __restrict__ K,
                     const __half* __restrict__ Vt,
                     __nv_bfloat16* __restrict__ Ao)
{
    extern __shared__ char smem_raw[];
    const uint32_t sb = smem_u32(smem_raw);
    const int tid  = threadIdx.x;
    const int wid  = tid >> 5;
    const int lane = tid & 31;
    const int bh   = blockIdx.z * H_ + blockIdx.y;
    const int q0   = blockIdx.x * 128;

    // ---- Q load: 128 rows x 128B, 4 chunks/thread ----
    {
        int r  = tid >> 1;
        int lc = (tid & 1) * 4;
        const __half* qrow = Q + ((size_t)bh * S_ + q0 + r) * HD_;
#pragma unroll
        for (int c = 0; c < 4; c++) {
            uint32_t off = SW128((uint32_t)(r * 128 + (lc + c) * 16));
            cp_async16(sb + off, qrow + (lc + c) * 8);
        }
    }

    // KV stage loader: K 64x128B + Vt 64x128B, 4 chunks/thread
    auto load_kv = [&](int kt, int s) {
        int r  = tid >> 2;            // 0..63
        int c2 = (tid & 3) * 2;
        const __half* krow = K + ((size_t)bh * S_ + kt + r) * HD_;
        const __half* vrow = Vt + ((size_t)bh * HD_ + r) * S_ + kt;
        const uint32_t st = sb + AST(s);
#pragma unroll
        for (int cc = 0; cc < 2; cc++) {
            int c = c2 + cc;
            uint32_t off = SW128((uint32_t)(r * 128 + c * 16));
            cp_async16(st + off,        krow + c * 8);
            cp_async16(st + 8192 + off, vrow + c * 8);
        }
    };

    load_kv(0, 0);
    cp_commit();

    const int a_row = wid * 16 + (lane & 15);
    const int a_cb  = (lane >> 4) << 4;
    const int b_row = (lane & 7) + ((lane >> 4) << 3);
    const int b_cb  = ((lane >> 3) & 1) << 4;

    float m0 = -1e30f, m1 = -1e30f, l0 = 0.0f, l1 = 0.0f;
    float oacc[8][4];
#pragma unroll
    for (int j = 0; j < 8; j++)
#pragma unroll
        for (int e = 0; e < 4; e++) oacc[j][e] = 0.0f;

    for (int it = 0; it < S_ / 64; it++) {
        const int s = it & 1;
        if (it + 1 < S_ / 64) {
            load_kv((it + 1) * 64, s ^ 1);
            cp_commit();
            cp_wait<1>();
        } else {
            cp_wait<0>();
        }
        __syncthreads();

        const uint32_t stK = sb + AST(s);
        const uint32_t stV = stK + 8192;

        // ---- S = Q16 @ K16^T (single fp16 pass) ----
        float sacc[8][4];
#pragma unroll
        for (int j = 0; j < 8; j++)
#pragma unroll
            for (int e = 0; e < 4; e++) sacc[j][e] = 0.0f;

#pragma unroll
        for (int ks = 0; ks < 4; ks++) {
            uint32_t bk[4][4], af[4];
#pragma unroll
            for (int nt2 = 0; nt2 < 4; nt2++) {
                uint32_t off = SW128((uint32_t)((b_row + nt2 * 16) * 128 + ks * 32 + b_cb));
                ldmatrix_x4(bk[nt2], stK + off);
            }
            uint32_t aoff = SW128((uint32_t)(a_row * 128 + ks * 32 + a_cb));
            ldmatrix_x4(af, sb + aoff);
#pragma unroll
            for (int j = 0; j < 8; j++)
                mma_f16(sacc[j], af, &bk[j >> 1][(j & 1) * 2]);
        }

        // ---- online softmax (exp2 domain, 1/8 scale folded) ----
        float mx0 = -1e30f, mx1 = -1e30f;
#pragma unroll
        for (int j = 0; j < 8; j++) {
            mx0 = fmaxf(mx0, fmaxf(sacc[j][0], sacc[j][1]));
            mx1 = fmaxf(mx1, fmaxf(sacc[j][2], sacc[j][3]));
        }
        mx0 = fmaxf(mx0, __shfl_xor_sync(0xffffffffu, mx0, 1));
        mx0 = fmaxf(mx0, __shfl_xor_sync(0xffffffffu, mx0, 2));
        mx1 = fmaxf(mx1, __shfl_xor_sync(0xffffffffu, mx1, 1));
        mx1 = fmaxf(mx1, __shfl_xor_sync(0xffffffffu, mx1, 2));
        float mn0 = fmaxf(m0, mx0), mn1 = fmaxf(m1, mx1);
        float corr0 = exp2f((m0 - mn0) * SC_LOG2E);
        float corr1 = exp2f((m1 - mn1) * SC_LOG2E);
        m0 = mn0; m1 = mn1;

        uint32_t phi[8][2], plo[8][2];
        float rs0 = 0.0f, rs1 = 0.0f;
#pragma unroll
        for (int j = 0; j < 8; j++) {
            float p0 = exp2f((sacc[j][0] - m0) * SC_LOG2E);
            float p1 = exp2f((sacc[j][1] - m0) * SC_LOG2E);
            float p2 = exp2f((sacc[j][2] - m1) * SC_LOG2E);
            float p3 = exp2f((sacc[j][3] - m1) * SC_LOG2E);
            rs0 += p0 + p1;
            rs1 += p2 + p3;
            __half2 h01 = __float22half2_rn(make_float2(p0, p1));
            float2 hf = __half22float2(h01);
            __half2 l01 = __float22half2_rn(make_float2(p0 - hf.x, p1 - hf.y));
            phi[j][0] = *(uint32_t*)&h01;
            plo[j][0] = *(uint32_t*)&l01;
            __half2 h23 = __float22half2_rn(make_float2(p2, p3));
            float2 hf2 = __half22float2(h23);
            __half2 l23 = __float22half2_rn(make_float2(p2 - hf2.x, p3 - hf2.y));
            phi[j][1] = *(uint32_t*)&h23;
            plo[j][1] = *(uint32_t*)&l23;
        }
        rs0 += __shfl_xor_sync(0xffffffffu, rs0, 1);
        rs0 += __shfl_xor_sync(0xffffffffu, rs0, 2);
        rs1 += __shfl_xor_sync(0xffffffffu, rs1, 1);
        rs1 += __shfl_xor_sync(0xffffffffu, rs1, 2);
        l0 = l0 * corr0 + rs0;
        l1 = l1 * corr1 + rs1;
#pragma unroll
        for (int j = 0; j < 8; j++) {
            oacc[j][0] *= corr0; oacc[j][1] *= corr0;
            oacc[j][2] *= corr1; oacc[j][3] *= corr1;
        }

        // ---- O += Phi@V16 + Plo@V16 ----
#pragma unroll
        for (int kc = 0; kc < 4; kc++) {
            uint32_t bv[4][4];
#pragma unroll
            for (int nt2 = 0; nt2 < 4; nt2++) {
                uint32_t off = SW128((uint32_t)((b_row + nt2 * 16) * 128 + kc * 32 + b_cb));
                ldmatrix_x4(bv[nt2], stV + off);
            }
            uint32_t ah[4] = {phi[2 * kc][0], phi[2 * kc][1], phi[2 * kc + 1][0], phi[2 * kc + 1][1]};
            uint32_t al[4] = {plo[2 * kc][0], plo[2 * kc][1], plo[2 * kc + 1][0], plo[2 * kc + 1][1]};
#pragma unroll
            for (int j = 0; j < 8; j++) {
                mma_f16(oacc[j], ah, &bv[j >> 1][(j & 1) * 2]);
                mma_f16(oacc[j], al, &bv[j >> 1][(j & 1) * 2]);
            }
        }
        __syncthreads();
    }

    // ---- epilogue: write bf16 [hi|hi|lo] rows of g_a2 directly ----
    const int b = blockIdx.z, h = blockIdx.y;
    const float inv0 = 1.0f / l0, inv1 = 1.0f / l1;
    const int qr = q0 + wid * 16 + (lane >> 2);
    const int nc = h * HD_ + (lane & 3) * 2;
    __nv_bfloat16* row0 = Ao + (size_t)(b * S_ + qr) * KP_;
    __nv_bfloat16* row1 = row0 + (size_t)8 * KP_;
#pragma unroll
    for (int j = 0; j < 8; j++) {
        const int col = nc + j * 8;
        {
            float2 v = {oacc[j][0] * inv0, oacc[j][1] * inv0};
            __nv_bfloat162 hi = __float22bfloat162_rn(v);
            float2 hf = __bfloat1622float2(hi);
            __nv_bfloat162 lo = __float22bfloat162_rn(make_float2(v.x - hf.x, v.y - hf.y));
            *(__nv_bfloat162*)(row0 + col)          = hi;
            *(__nv_bfloat162*)(row0 + D_ + col)     = hi;
            *(__nv_bfloat162*)(row0 + 2 * D_ + col) = lo;
        }
        {
            float2 v = {oacc[j][2] * inv1, oacc[j][3] * inv1};
            __nv_bfloat162 hi = __float22bfloat162_rn(v);
            float2 hf = __bfloat1622float2(hi);
            __nv_bfloat162 lo = __float22bfloat162_rn(make_float2(v.x - hf.x, v.y - hf.y));
            *(__nv_bfloat162*)(row1 + col)          = hi;
            *(__nv_bfloat162*)(row1 + D_ + col)     = hi;
            *(__nv_bfloat162*)(row1 + 2 * D_ + col) = lo;
        }
    }
}

// ---------------------------------------------------------------------------
// Launch
// ---------------------------------------------------------------------------
extern "C" void kernel_launch(void* const* d_in, const int* in_sizes, int n_in,
                              void* d_out, int out_size)
{
    const float* x  = (const float*)d_in[0];
    const float* wq = (const float*)d_in[1];
    const float* bq = (const float*)d_in[2];
    const float* wk = (const float*)d_in[3];
    const float* bk = (const float*)d_in[4];
    const float* wv = (const float*)d_in[5];
    const float* bv = (const float*)d_in[6];
    const float* wo = (const float*)d_in[7];
    const float* bo = (const float*)d_in[8];
    float* out = (float*)d_out;

    __nv_bfloat16 *axp, *a2p, *wqp, *wkp, *wvp, *wop;
    __half *qhp, *khp, *vtp;
    cudaGetSymbolAddress((void**)&axp, g_ax);
    cudaGetSymbolAddress((void**)&a2p, g_a2);
    cudaGetSymbolAddress((void**)&wqp, g_wq);
    cudaGetSymbolAddress((void**)&wkp, g_wk);
    cudaGetSymbolAddress((void**)&wvp, g_wv);
    cudaGetSymbolAddress((void**)&wop, g_wo);
    cudaGetSymbolAddress((void**)&qhp, g_qh);
    cudaGetSymbolAddress((void**)&khp, g_kh);
    cudaGetSymbolAddress((void**)&vtp, g_vt);

    cudaFuncSetAttribute(attn_mma_kernel,
                         cudaFuncAttributeMaxDynamicSharedMemorySize, ATTN_SMEM);
    cudaFuncSetAttribute(tc_gemm_kernel<0>,
                         cudaFuncAttributeMaxDynamicSharedMemorySize, GEMM_SMEM);
    cudaFuncSetAttribute(tc_gemm_kernel<1>,
                         cudaFuncAttributeMaxDynamicSharedMemorySize, GEMM_SMEM);
    cudaFuncSetAttribute(tc_gemm_kernel<2>,
                         cudaFuncAttributeMaxDynamicSharedMemorySize, GEMM_SMEM);

    split_a_kernel<<<(MTOT * D_ / 4) / 256, 256>>>(x, axp);
    split_w_kernel<<<(D_ * D_ / 4) / 256, 256>>>(wq, wqp);
    split_w_kernel<<<(D_ * D_ / 4) / 256, 256>>>(wk, wkp);
    split_w_kernel<<<(D_ * D_ / 4) / 256, 256>>>(wv, wvp);
    split_w_kernel<<<(D_ * D_ / 4) / 256, 256>>>(wo, wop);

    dim3 ggrid(D_ / 128, MTOT / 128);   // (6, 64)
    tc_gemm_kernel<1><<<ggrid, 256, GEMM_SMEM>>>(axp, wqp, bq, nullptr, qhp);
    tc_gemm_kernel<1><<<ggrid, 256, GEMM_SMEM>>>(axp, wkp, bk, nullptr, khp);
    tc_gemm_kernel<2><<<ggrid, 256, GEMM_SMEM>>>(axp, wvp, bv, nullptr, vtp);

    attn_mma_kernel<<<dim3(S_ / 128, H_, B_), 256, ATTN_SMEM>>>(qhp, khp, vtp, a2p);

    tc_gemm_kernel<0><<<ggrid, 256, GEMM_SMEM>>>(a2p, wop, bo, out, nullptr);
}

// round 7
// speedup vs baseline: 4.6281x; 1.3852x over previous
#include <cuda_runtime.h>
#include <cuda_bf16.h>
#include <cuda_fp16.h>
#include <math.h>
#include <stdint.h>

// Problem constants
#define B_   8
#define S_   1024
#define D_   768
#define H_   12
#define HD_  64
#define BH_  (B_ * H_)       // 96
#define MTOT (B_ * S_)       // 8192
#define KP_  (2 * D_)        // 1536 : A=[hi16|lo16], W=[w16|w16]

// ---------------------------------------------------------------------------
// Scratch (device globals — no runtime allocation allowed)
// ---------------------------------------------------------------------------
__device__ __half g_ax[(size_t)MTOT * KP_];    // split(x) fp16 [hi|lo]
__device__ __half g_a2[(size_t)MTOT * KP_];    // split(attn out), written by attn
__device__ __half g_wq[(size_t)D_ * KP_];      // W^T fp16 [n, k'] = [w|w]
__device__ __half g_wk[(size_t)D_ * KP_];
__device__ __half g_wv[(size_t)D_ * KP_];
__device__ __half g_wo[(size_t)D_ * KP_];
__device__ __half g_qh[(size_t)BH_ * S_ * HD_];       // Q fp16 [bh, s, d]
__device__ __half g_kh[(size_t)BH_ * S_ * HD_];       // K fp16 [bh, s, d]
__device__ __half g_vt[(size_t)BH_ * HD_ * S_];       // V^T fp16 [bh, d, s]

// ---------------------------------------------------------------------------
// PTX helpers (standard sm_80+ instructions only)
// ---------------------------------------------------------------------------
__device__ __forceinline__ uint32_t smem_u32(const void* p) {
    uint32_t a;
    asm("{ .reg .u64 t; cvta.to.shared.u64 t, %1; cvt.u32.u64 %0, t; }" : "=r"(a) : "l"(p));
    return a;
}
__device__ __forceinline__ void cp_async16(uint32_t dst, const void* src) {
    asm volatile("cp.async.cg.shared.global [%0], [%1], 16;" :: "r"(dst), "l"(src) : "memory");
}
__device__ __forceinline__ void cp_commit() {
    asm volatile("cp.async.commit_group;" ::: "memory");
}
template <int N>
__device__ __forceinline__ void cp_wait() {
    asm volatile("cp.async.wait_group %0;" :: "n"(N) : "memory");
}
__device__ __forceinline__ void ldmatrix_x4(uint32_t* r, uint32_t addr) {
    asm volatile("ldmatrix.sync.aligned.m8n8.x4.shared.b16 {%0,%1,%2,%3}, [%4];"
        : "=r"(r[0]), "=r"(r[1]), "=r"(r[2]), "=r"(r[3]) : "r"(addr));
}
__device__ __forceinline__ void mma_f16(float* c, const uint32_t* a, const uint32_t* b) {
    asm volatile(
        "mma.sync.aligned.m16n8k16.row.col.f32.f16.f16.f32 "
        "{%0,%1,%2,%3}, {%4,%5,%6,%7}, {%8,%9}, {%0,%1,%2,%3};"
        : "+f"(c[0]), "+f"(c[1]), "+f"(c[2]), "+f"(c[3])
        : "r"(a[0]), "r"(a[1]), "r"(a[2]), "r"(a[3]), "r"(b[0]), "r"(b[1]));
}

// SW128 swizzle for 128B rows (16B-chunk granularity)
#define SW128(off) ((off) ^ (((off) >> 3) & 0x70))

// ---------------------------------------------------------------------------
// Split kernels: fp32 -> fp16, A rows = [hi | lo], W^T rows = [w | w]
// ---------------------------------------------------------------------------
__global__ __launch_bounds__(256) void split_a_kernel(const float* __restrict__ in,
                                                      __half* __restrict__ out)
{
    int idx = blockIdx.x * blockDim.x + threadIdx.x;
    int m  = idx / (D_ / 4);
    int k4 = (idx % (D_ / 4)) * 4;
    float4 x = *(const float4*)(in + (size_t)m * D_ + k4);
    float xs[4] = {x.x, x.y, x.z, x.w};
    __half hi[4], lo[4];
#pragma unroll
    for (int i = 0; i < 4; i++) {
        hi[i] = __float2half_rn(xs[i]);
        lo[i] = __float2half_rn(xs[i] - __half2float(hi[i]));
    }
    uint2 hp, lp;
    ((__half2*)&hp)[0] = __halves2half2(hi[0], hi[1]);
    ((__half2*)&hp)[1] = __halves2half2(hi[2], hi[3]);
    ((__half2*)&lp)[0] = __halves2half2(lo[0], lo[1]);
    ((__half2*)&lp)[1] = __halves2half2(lo[2], lo[3]);
    __half* row = out + (size_t)m * KP_;
    *(uint2*)(row + k4)      = hp;   // hi
    *(uint2*)(row + D_ + k4) = lp;   // lo
}

// W [K=768, N=768] fp32 -> W' fp16 [n, k'] duplicated [w | w]
__global__ __launch_bounds__(256) void split_w_kernel(const float* __restrict__ w,
                                                      __half* __restrict__ out)
{
    int idx = blockIdx.x * blockDim.x + threadIdx.x;
    int n  = idx / (D_ / 4);
    int k4 = (idx % (D_ / 4)) * 4;
    __half v[4];
#pragma unroll
    for (int i = 0; i < 4; i++)
        v[i] = __float2half_rn(w[(size_t)(k4 + i) * D_ + n]);
    uint2 p;
    ((__half2*)&p)[0] = __halves2half2(v[0], v[1]);
    ((__half2*)&p)[1] = __halves2half2(v[2], v[3]);
    __half* row = out + (size_t)n * KP_;
    *(uint2*)(row + k4)      = p;
    *(uint2*)(row + D_ + k4) = p;
}

// ---------------------------------------------------------------------------
// mma.sync fp16x2 GEMM: C[M, N=768] = A'[M, 1536] @ W'^T + bias.
// MODE 0: fp32 row-major [M,768] (output projection, -> d_out)
// MODE 1: fp16 [bh, s, 64]  (Q, K)
// MODE 2: fp16 V^T [bh, d, s]  (V)
// ---------------------------------------------------------------------------
#define BK_        64
#define NT_        (KP_ / BK_)            // 24
#define TILE_B     (128 * 128)            // 16KB
#define GEMM_SMEM  (4 * TILE_B)           // 64KB

template <int MODE>
__global__ __launch_bounds__(256)
void tc_gemm_kernel(const __half* __restrict__ A,
                    const __half* __restrict__ W,
                    const float* __restrict__ bias,
                    float* __restrict__ outf, __half* __restrict__ outh)
{
    extern __shared__ char smem_raw[];
    const uint32_t sbase = smem_u32(smem_raw);
    const int tid  = threadIdx.x;
    const int wid  = tid >> 5;
    const int lane = tid & 31;
    const int wm   = (wid & 1) * 64;
    const int wn   = (wid >> 1) * 32;
    const int m0   = blockIdx.y * 128;
    const int n0   = blockIdx.x * 128;

    const int lr = tid >> 1;
    const int lc = (tid & 1) * 4;

    float acc[4][4][4];
#pragma unroll
    for (int i = 0; i < 4; i++)
#pragma unroll
        for (int j = 0; j < 4; j++)
#pragma unroll
            for (int e = 0; e < 4; e++) acc[i][j][e] = 0.0f;

    auto load_stage = [&](int it, int s) {
        const uint32_t sA = sbase + s * 2 * TILE_B;
        const uint32_t sB = sA + TILE_B;
        const int k0 = it * BK_;
        const __half* Ag = A + (size_t)(m0 + lr) * KP_ + k0 + lc * 8;
        const __half* Wg = W + (size_t)(n0 + lr) * KP_ + k0 + lc * 8;
#pragma unroll
        for (int c = 0; c < 4; c++) {
            uint32_t off = SW128((uint32_t)(lr * 128 + (lc + c) * 16));
            cp_async16(sA + off, Ag + c * 8);
            cp_async16(sB + off, Wg + c * 8);
        }
    };

    load_stage(0, 0);
    cp_commit();

    const int a_row = wm + (lane & 15);
    const int a_cb  = (lane >> 4) << 4;
    const int b_row = wn + (lane & 7) + ((lane >> 4) << 3);
    const int b_cb  = ((lane >> 3) & 1) << 4;

    for (int it = 0; it < NT_; it++) {
        const int s = it & 1;
        if (it + 1 < NT_) {
            load_stage(it + 1, s ^ 1);
            cp_commit();
            cp_wait<1>();
        } else {
            cp_wait<0>();
        }
        __syncthreads();

        const uint32_t sA = sbase + s * 2 * TILE_B;
        const uint32_t sB = sA + TILE_B;

#pragma unroll
        for (int ks = 0; ks < BK_ / 16; ks++) {
            uint32_t af[4][4], bf[2][4];
#pragma unroll
            for (int mt = 0; mt < 4; mt++) {
                uint32_t off = SW128((uint32_t)((a_row + mt * 16) * 128 + ks * 32 + a_cb));
                ldmatrix_x4(af[mt], sA + off);
            }
#pragma unroll
            for (int nt2 = 0; nt2 < 2; nt2++) {
                uint32_t off = SW128((uint32_t)((b_row + nt2 * 16) * 128 + ks * 32 + b_cb));
                ldmatrix_x4(bf[nt2], sB + off);
            }
#pragma unroll
            for (int mt = 0; mt < 4; mt++)
#pragma unroll
                for (int nt = 0; nt < 4; nt++)
                    mma_f16(acc[mt][nt], af[mt], &bf[nt >> 1][(nt & 1) * 2]);
        }
        __syncthreads();
    }

#pragma unroll
    for (int mt = 0; mt < 4; mt++) {
#pragma unroll
        for (int nt = 0; nt < 4; nt++) {
            int m = m0 + wm + mt * 16 + (lane >> 2);
            int n = n0 + wn + nt * 8 + (lane & 3) * 2;
            float2 bv = *(const float2*)(bias + n);
            float2 v0 = {acc[mt][nt][0] + bv.x, acc[mt][nt][1] + bv.y};
            float2 v1 = {acc[mt][nt][2] + bv.x, acc[mt][nt][3] + bv.y};
            if (MODE == 0) {
                *(float2*)(outf + (size_t)m * D_ + n) = v0;
                *(float2*)(outf + (size_t)(m + 8) * D_ + n) = v1;
            } else {
                int b = m >> 10, sq = m & 1023;
                int h = n >> 6, d = n & 63;
                int bh = b * H_ + h;
                if (MODE == 1) {
                    size_t base = ((size_t)bh * S_ + sq) * HD_ + d;
                    *(__half2*)(outh + base)            = __float22half2_rn(v0);
                    *(__half2*)(outh + base + 8 * HD_)  = __float22half2_rn(v1);
                } else {
                    size_t r0 = ((size_t)bh * HD_ + d) * S_ + sq;
                    outh[r0]          = __float2half_rn(v0.x);
                    outh[r0 + S_]     = __float2half_rn(v0.y);
                    outh[r0 + 8]      = __float2half_rn(v1.x);
                    outh[r0 + S_ + 8] = __float2half_rn(v1.y);
                }
            }
        }
    }
}

// ---------------------------------------------------------------------------
// Tensor-core flash attention, fp16 operands.
// S = Q16 @ K16^T (1 pass). O = P16 @ V16 (1 pass).
// smem: Q plane 16KB + 2 stages x (K 8KB + Vt 8KB) = 48KB.
// Epilogue writes fp16 [hi|lo] rows of g_a2 directly (O-proj A operand).
// ---------------------------------------------------------------------------
#define AST(s)  (16384 + (s) * 16384)
#define ATTN_SMEM 49152
#define SC_LOG2E 0.18033688f    // 0.125 * log2(e)

__global__ __launch_bounds__(256)
void attn_mma_kernel(const __half* __restrict__ Q,
                     const __half* __restrict__ K,
                     const __half* __restrict__ Vt,
                     __half* __restrict__ Ao)
{
    extern __shared__ char smem_raw[];
    const uint32_t sb = smem_u32(smem_raw);
    const int tid  = threadIdx.x;
    const int wid  = tid >> 5;
    const int lane = tid & 31;
    const int bh   = blockIdx.z * H_ + blockIdx.y;
    const int q0   = blockIdx.x * 128;

    // ---- Q load: 128 rows x 128B, 4 chunks/thread ----
    {
        int r  = tid >> 1;
        int lc = (tid & 1) * 4;
        const __half* qrow = Q + ((size_t)bh * S_ + q0 + r) * HD_;
#pragma unroll
        for (int c = 0; c < 4; c++) {
            uint32_t off = SW128((uint32_t)(r * 128 + (lc + c) * 16));
            cp_async16(sb + off, qrow + (lc + c) * 8);
        }
    }

    // KV stage loader: K 64x128B + Vt 64x128B, 4 chunks/thread
    auto load_kv = [&](int kt, int s) {
        int r  = tid >> 2;            // 0..63
        int c2 = (tid & 3) * 2;
        const __half* krow = K + ((size_t)bh * S_ + kt + r) * HD_;
        const __half* vrow = Vt + ((size_t)bh * HD_ + r) * S_ + kt;
        const uint32_t st = sb + AST(s);
#pragma unroll
        for (int cc = 0; cc < 2; cc++) {
            int c = c2 + cc;
            uint32_t off = SW128((uint32_t)(r * 128 + c * 16));
            cp_async16(st + off,        krow + c * 8);
            cp_async16(st + 8192 + off, vrow + c * 8);
        }
    };

    load_kv(0, 0);
    cp_commit();

    const int a_row = wid * 16 + (lane & 15);
    const int a_cb  = (lane >> 4) << 4;
    const int b_row = (lane & 7) + ((lane >> 4) << 3);
    const int b_cb  = ((lane >> 3) & 1) << 4;

    float m0 = -1e30f, m1 = -1e30f, l0 = 0.0f, l1 = 0.0f;
    float oacc[8][4];
#pragma unroll
    for (int j = 0; j < 8; j++)
#pragma unroll
        for (int e = 0; e < 4; e++) oacc[j][e] = 0.0f;

    for (int it = 0; it < S_ / 64; it++) {
        const int s = it & 1;
        if (it + 1 < S_ / 64) {
            load_kv((it + 1) * 64, s ^ 1);
            cp_commit();
            cp_wait<1>();
        } else {
            cp_wait<0>();
        }
        __syncthreads();

        const uint32_t stK = sb + AST(s);
        const uint32_t stV = stK + 8192;

        // ---- S = Q16 @ K16^T ----
        float sacc[8][4];
#pragma unroll
        for (int j = 0; j < 8; j++)
#pragma unroll
            for (int e = 0; e < 4; e++) sacc[j][e] = 0.0f;

#pragma unroll
        for (int ks = 0; ks < 4; ks++) {
            uint32_t bk[4][4], af[4];
#pragma unroll
            for (int nt2 = 0; nt2 < 4; nt2++) {
                uint32_t off = SW128((uint32_t)((b_row + nt2 * 16) * 128 + ks * 32 + b_cb));
                ldmatrix_x4(bk[nt2], stK + off);
            }
            uint32_t aoff = SW128((uint32_t)(a_row * 128 + ks * 32 + a_cb));
            ldmatrix_x4(af, sb + aoff);
#pragma unroll
            for (int j = 0; j < 8; j++)
                mma_f16(sacc[j], af, &bk[j >> 1][(j & 1) * 2]);
        }

        // ---- online softmax (exp2 domain, 1/8 scale folded) ----
        float mx0 = -1e30f, mx1 = -1e30f;
#pragma unroll
        for (int j = 0; j < 8; j++) {
            mx0 = fmaxf(mx0, fmaxf(sacc[j][0], sacc[j][1]));
            mx1 = fmaxf(mx1, fmaxf(sacc[j][2], sacc[j][3]));
        }
        mx0 = fmaxf(mx0, __shfl_xor_sync(0xffffffffu, mx0, 1));
        mx0 = fmaxf(mx0, __shfl_xor_sync(0xffffffffu, mx0, 2));
        mx1 = fmaxf(mx1, __shfl_xor_sync(0xffffffffu, mx1, 1));
        mx1 = fmaxf(mx1, __shfl_xor_sync(0xffffffffu, mx1, 2));
        float mn0 = fmaxf(m0, mx0), mn1 = fmaxf(m1, mx1);
        float corr0 = exp2f((m0 - mn0) * SC_LOG2E);
        float corr1 = exp2f((m1 - mn1) * SC_LOG2E);
        m0 = mn0; m1 = mn1;

        uint32_t pf[8][2];
        float rs0 = 0.0f, rs1 = 0.0f;
#pragma unroll
        for (int j = 0; j < 8; j++) {
            float p0 = exp2f((sacc[j][0] - m0) * SC_LOG2E);
            float p1 = exp2f((sacc[j][1] - m0) * SC_LOG2E);
            float p2 = exp2f((sacc[j][2] - m1) * SC_LOG2E);
            float p3 = exp2f((sacc[j][3] - m1) * SC_LOG2E);
            rs0 += p0 + p1;
            rs1 += p2 + p3;
            __half2 h01 = __float22half2_rn(make_float2(p0, p1));
            __half2 h23 = __float22half2_rn(make_float2(p2, p3));
            pf[j][0] = *(uint32_t*)&h01;
            pf[j][1] = *(uint32_t*)&h23;
        }
        rs0 += __shfl_xor_sync(0xffffffffu, rs0, 1);
        rs0 += __shfl_xor_sync(0xffffffffu, rs0, 2);
        rs1 += __shfl_xor_sync(0xffffffffu, rs1, 1);
        rs1 += __shfl_xor_sync(0xffffffffu, rs1, 2);
        l0 = l0 * corr0 + rs0;
        l1 = l1 * corr1 + rs1;
#pragma unroll
        for (int j = 0; j < 8; j++) {
            oacc[j][0] *= corr0; oacc[j][1] *= corr0;
            oacc[j][2] *= corr1; oacc[j][3] *= corr1;
        }

        // ---- O += P16 @ V16 ----
#pragma unroll
        for (int kc = 0; kc < 4; kc++) {
            uint32_t bv[4][4];
#pragma unroll
            for (int nt2 = 0; nt2 < 4; nt2++) {
                uint32_t off = SW128((uint32_t)((b_row + nt2 * 16) * 128 + kc * 32 + b_cb));
                ldmatrix_x4(bv[nt2], stV + off);
            }
            uint32_t ap[4] = {pf[2 * kc][0], pf[2 * kc][1], pf[2 * kc + 1][0], pf[2 * kc + 1][1]};
#pragma unroll
            for (int j = 0; j < 8; j++)
                mma_f16(oacc[j], ap, &bv[j >> 1][(j & 1) * 2]);
        }
        __syncthreads();
    }

    // ---- epilogue: write fp16 [hi|lo] rows of g_a2 directly ----
    const int b = blockIdx.z, h = blockIdx.y;
    const float inv0 = 1.0f / l0, inv1 = 1.0f / l1;
    const int qr = q0 + wid * 16 + (lane >> 2);
    const int nc = h * HD_ + (lane & 3) * 2;
    __half* row0 = Ao + (size_t)(b * S_ + qr) * KP_;
    __half* row1 = row0 + (size_t)8 * KP_;
#pragma unroll
    for (int j = 0; j < 8; j++) {
        const int col = nc + j * 8;
        {
            float2 v = {oacc[j][0] * inv0, oacc[j][1] * inv0};
            __half2 hi = __float22half2_rn(v);
            float2 hf = __half22float2(hi);
            __half2 lo = __float22half2_rn(make_float2(v.x - hf.x, v.y - hf.y));
            *(__half2*)(row0 + col)      = hi;
            *(__half2*)(row0 + D_ + col) = lo;
        }
        {
            float2 v = {oacc[j][2] * inv1, oacc[j][3] * inv1};
            __half2 hi = __float22half2_rn(v);
            float2 hf = __half22float2(hi);
            __half2 lo = __float22half2_rn(make_float2(v.x - hf.x, v.y - hf.y));
            *(__half2*)(row1 + col)      = hi;
            *(__half2*)(row1 + D_ + col) = lo;
        }
    }
}

// ---------------------------------------------------------------------------
// Launch
// ---------------------------------------------------------------------------
extern "C" void kernel_launch(void* const* d_in, const int* in_sizes, int n_in,
                              void* d_out, int out_size)
{
    const float* x  = (const float*)d_in[0];
    const float* wq = (const float*)d_in[1];
    const float* bq = (const float*)d_in[2];
    const float* wk = (const float*)d_in[3];
    const float* bk = (const float*)d_in[4];
    const float* wv = (const float*)d_in[5];
    const float* bv = (const float*)d_in[6];
    const float* wo = (const float*)d_in[7];
    const float* bo = (const float*)d_in[8];
    float* out = (float*)d_out;

    __half *axp, *a2p, *wqp, *wkp, *wvp, *wop, *qhp, *khp, *vtp;
    cudaGetSymbolAddress((void**)&axp, g_ax);
    cudaGetSymbolAddress((void**)&a2p, g_a2);
    cudaGetSymbolAddress((void**)&wqp, g_wq);
    cudaGetSymbolAddress((void**)&wkp, g_wk);
    cudaGetSymbolAddress((void**)&wvp, g_wv);
    cudaGetSymbolAddress((void**)&wop, g_wo);
    cudaGetSymbolAddress((void**)&qhp, g_qh);
    cudaGetSymbolAddress((void**)&khp, g_kh);
    cudaGetSymbolAddress((void**)&vtp, g_vt);

    cudaFuncSetAttribute(attn_mma_kernel,
                         cudaFuncAttributeMaxDynamicSharedMemorySize, ATTN_SMEM);
    cudaFuncSetAttribute(tc_gemm_kernel<0>,
                         cudaFuncAttributeMaxDynamicSharedMemorySize, GEMM_SMEM);
    cudaFuncSetAttribute(tc_gemm_kernel<1>,
                         cudaFuncAttributeMaxDynamicSharedMemorySize, GEMM_SMEM);
    cudaFuncSetAttribute(tc_gemm_kernel<2>,
                         cudaFuncAttributeMaxDynamicSharedMemorySize, GEMM_SMEM);

    split_a_kernel<<<(MTOT * D_ / 4) / 256, 256>>>(x, axp);
    split_w_kernel<<<(D_ * D_ / 4) / 256, 256>>>(wq, wqp);
    split_w_kernel<<<(D_ * D_ / 4) / 256, 256>>>(wk, wkp);
    split_w_kernel<<<(D_ * D_ / 4) / 256, 256>>>(wv, wvp);
    split_w_kernel<<<(D_ * D_ / 4) / 256, 256>>>(wo, wop);

    dim3 ggrid(D_ / 128, MTOT / 128);   // (6, 64)
    tc_gemm_kernel<1><<<ggrid, 256, GEMM_SMEM>>>(axp, wqp, bq, nullptr, qhp);
    tc_gemm_kernel<1><<<ggrid, 256, GEMM_SMEM>>>(axp, wkp, bk, nullptr, khp);
    tc_gemm_kernel<2><<<ggrid, 256, GEMM_SMEM>>>(axp, wvp, bv, nullptr, vtp);

    attn_mma_kernel<<<dim3(S_ / 128, H_, B_), 256, ATTN_SMEM>>>(qhp, khp, vtp, a2p);

    tc_gemm_kernel<0><<<ggrid, 256, GEMM_SMEM>>>(a2p, wop, bo, out, nullptr);
}

// round 8
// speedup vs baseline: 7.4506x; 1.6099x over previous
#include <cuda_runtime.h>
#include <cuda_fp16.h>
#include <math.h>
#include <stdint.h>

// Problem constants
#define B_   8
#define S_   1024
#define D_   768
#define H_   12
#define HD_  64
#define BH_  (B_ * H_)       // 96
#define MTOT (B_ * S_)       // 8192
#define NQKV (3 * D_)        // 2304

// ---------------------------------------------------------------------------
// Scratch (device globals — no runtime allocation allowed)
// ---------------------------------------------------------------------------
__device__ __half g_ax[(size_t)MTOT * D_];        // fp16(x)
__device__ __half g_a2[(size_t)MTOT * D_];        // fp16(attn out)
__device__ __half g_wqkv[(size_t)NQKV * D_];      // fp16 W^T rows: [wq | wk | wv]
__device__ __half g_wo[(size_t)D_ * D_];          // fp16 wo^T [n, k]
__device__ float  g_bqkv[NQKV];                   // concat bias
__device__ __half g_qh[(size_t)BH_ * S_ * HD_];   // Q fp16 [bh, s, d]
__device__ __half g_kh[(size_t)BH_ * S_ * HD_];   // K fp16 [bh, s, d]
__device__ __half g_vt[(size_t)BH_ * HD_ * S_];   // V^T fp16 [bh, d, s]

// ---------------------------------------------------------------------------
// PTX helpers (standard sm_80+ instructions only)
// ---------------------------------------------------------------------------
__device__ __forceinline__ uint32_t smem_u32(const void* p) {
    uint32_t a;
    asm("{ .reg .u64 t; cvta.to.shared.u64 t, %1; cvt.u32.u64 %0, t; }" : "=r"(a) : "l"(p));
    return a;
}
__device__ __forceinline__ void cp_async16(uint32_t dst, const void* src) {
    asm volatile("cp.async.cg.shared.global [%0], [%1], 16;" :: "r"(dst), "l"(src) : "memory");
}
__device__ __forceinline__ void cp_commit() {
    asm volatile("cp.async.commit_group;" ::: "memory");
}
template <int N>
__device__ __forceinline__ void cp_wait() {
    asm volatile("cp.async.wait_group %0;" :: "n"(N) : "memory");
}
__device__ __forceinline__ void ldmatrix_x4(uint32_t* r, uint32_t addr) {
    asm volatile("ldmatrix.sync.aligned.m8n8.x4.shared.b16 {%0,%1,%2,%3}, [%4];"
        : "=r"(r[0]), "=r"(r[1]), "=r"(r[2]), "=r"(r[3]) : "r"(addr));
}
__device__ __forceinline__ void mma_f16(float* c, const uint32_t* a, const uint32_t* b) {
    asm volatile(
        "mma.sync.aligned.m16n8k16.row.col.f32.f16.f16.f32 "
        "{%0,%1,%2,%3}, {%4,%5,%6,%7}, {%8,%9}, {%0,%1,%2,%3};"
        : "+f"(c[0]), "+f"(c[1]), "+f"(c[2]), "+f"(c[3])
        : "r"(a[0]), "r"(a[1]), "r"(a[2]), "r"(a[3]), "r"(b[0]), "r"(b[1]));
}

// SW128 swizzle for 128B rows (16B-chunk granularity)
#define SW128(off) ((off) ^ (((off) >> 3) & 0x70))

// ---------------------------------------------------------------------------
// Conversion kernels
// ---------------------------------------------------------------------------
__global__ __launch_bounds__(256) void conv_a_kernel(const float* __restrict__ in,
                                                     __half* __restrict__ out)
{
    int idx = blockIdx.x * blockDim.x + threadIdx.x;   // one per 4 elems
    float4 x = *(const float4*)(in + (size_t)idx * 4);
    uint2 p;
    ((__half2*)&p)[0] = __float22half2_rn(make_float2(x.x, x.y));
    ((__half2*)&p)[1] = __float22half2_rn(make_float2(x.z, x.w));
    *(uint2*)(out + (size_t)idx * 4) = p;
}

// W [K=768, N=768] fp32 -> W' fp16 [n, k] (transposed)
__global__ __launch_bounds__(256) void conv_w_kernel(const float* __restrict__ w,
                                                     __half* __restrict__ out)
{
    int idx = blockIdx.x * blockDim.x + threadIdx.x;
    int n  = idx / (D_ / 4);
    int k4 = (idx % (D_ / 4)) * 4;
    __half v[4];
#pragma unroll
    for (int i = 0; i < 4; i++)
        v[i] = __float2half_rn(w[(size_t)(k4 + i) * D_ + n]);
    uint2 p;
    ((__half2*)&p)[0] = __halves2half2(v[0], v[1]);
    ((__half2*)&p)[1] = __halves2half2(v[2], v[3]);
    *(uint2*)(out + (size_t)n * D_ + k4) = p;
}

__global__ void concat_bias_kernel(const float* __restrict__ bq,
                                   const float* __restrict__ bk,
                                   const float* __restrict__ bv,
                                   float* __restrict__ out)
{
    int i = blockIdx.x * blockDim.x + threadIdx.x;
    if (i < NQKV)
        out[i] = (i < D_) ? bq[i] : (i < 2 * D_ ? bk[i - D_] : bv[i - 2 * D_]);
}

// ---------------------------------------------------------------------------
// Common GEMM skeleton pieces: CTA 128x128, BK=64, K=768 (12 stages),
// 8 warps (2m x 4n), warp tile 64x32, fp16 mma -> fp32.
// ---------------------------------------------------------------------------
#define BK_        64
#define NT_        (D_ / BK_)             // 12
#define TILE_B     (128 * 128)            // 16KB
#define GEMM_SMEM  (4 * TILE_B)           // 64KB

#define GEMM_PROLOGUE()                                                       \
    extern __shared__ char smem_raw[];                                        \
    const uint32_t sbase = smem_u32(smem_raw);                                \
    const int tid  = threadIdx.x;                                             \
    const int wid  = tid >> 5;                                                \
    const int lane = tid & 31;                                                \
    const int wm   = (wid & 1) * 64;                                          \
    const int wn   = (wid >> 1) * 32;                                         \
    const int m0   = blockIdx.y * 128;                                        \
    const int n0   = blockIdx.x * 128;                                        \
    const int lr = tid >> 1;                                                  \
    const int lc = (tid & 1) * 4;                                             \
    float acc[4][4][4];                                                       \
    _Pragma("unroll")                                                         \
    for (int i = 0; i < 4; i++)                                               \
        _Pragma("unroll")                                                     \
        for (int j = 0; j < 4; j++)                                           \
            _Pragma("unroll")                                                 \
            for (int e = 0; e < 4; e++) acc[i][j][e] = 0.0f;                  \
    auto load_stage = [&](int it, int s) {                                    \
        const uint32_t sA = sbase + s * 2 * TILE_B;                           \
        const uint32_t sB = sA + TILE_B;                                      \
        const int k0 = it * BK_;                                              \
        const __half* Ag = A + (size_t)(m0 + lr) * D_ + k0 + lc * 8;          \
        const __half* Wg = W + (size_t)(n0 + lr) * D_ + k0 + lc * 8;          \
        _Pragma("unroll")                                                     \
        for (int c = 0; c < 4; c++) {                                         \
            uint32_t off = SW128((uint32_t)(lr * 128 + (lc + c) * 16));       \
            cp_async16(sA + off, Ag + c * 8);                                 \
            cp_async16(sB + off, Wg + c * 8);                                 \
        }                                                                     \
    };                                                                        \
    load_stage(0, 0);                                                         \
    cp_commit();                                                              \
    const int a_row = wm + (lane & 15);                                       \
    const int a_cb  = (lane >> 4) << 4;                                       \
    const int b_row = wn + (lane & 7) + ((lane >> 4) << 3);                   \
    const int b_cb  = ((lane >> 3) & 1) << 4;                                 \
    for (int it = 0; it < NT_; it++) {                                        \
        const int s = it & 1;                                                 \
        if (it + 1 < NT_) {                                                   \
            load_stage(it + 1, s ^ 1);                                        \
            cp_commit();                                                      \
            cp_wait<1>();                                                     \
        } else {                                                              \
            cp_wait<0>();                                                     \
        }                                                                     \
        __syncthreads();                                                      \
        const uint32_t sA = sbase + s * 2 * TILE_B;                           \
        const uint32_t sB = sA + TILE_B;                                      \
        _Pragma("unroll")                                                     \
        for (int ks = 0; ks < BK_ / 16; ks++) {                               \
            uint32_t af[4][4], bf[2][4];                                      \
            _Pragma("unroll")                                                 \
            for (int mt = 0; mt < 4; mt++) {                                  \
                uint32_t off = SW128((uint32_t)((a_row + mt * 16) * 128 + ks * 32 + a_cb)); \
                ldmatrix_x4(af[mt], sA + off);                                \
            }                                                                 \
            _Pragma("unroll")                                                 \
            for (int nt2 = 0; nt2 < 2; nt2++) {                               \
                uint32_t off = SW128((uint32_t)((b_row + nt2 * 16) * 128 + ks * 32 + b_cb)); \
                ldmatrix_x4(bf[nt2], sB + off);                               \
            }                                                                 \
            _Pragma("unroll")                                                 \
            for (int mt = 0; mt < 4; mt++)                                    \
                _Pragma("unroll")                                             \
                for (int nt = 0; nt < 4; nt++)                                \
                    mma_f16(acc[mt][nt], af[mt], &bf[nt >> 1][(nt & 1) * 2]); \
        }                                                                     \
        __syncthreads();                                                      \
    }

// ---------------------------------------------------------------------------
// Fused QKV GEMM: C[M, 2304] = Ax @ Wqkv^T + bqkv, scattered to Q/K fp16
// [bh,s,d] and V^T fp16 [bh,d,s]. `which` is uniform per CTA (128 | 768).
// ---------------------------------------------------------------------------
__global__ __launch_bounds__(256)
void tc_gemm_qkv(const __half* __restrict__ A,
                 const __half* __restrict__ W,
                 const float* __restrict__ bias,
                 __half* __restrict__ qo, __half* __restrict__ ko,
                 __half* __restrict__ vo)
{
    GEMM_PROLOGUE()

    const int which = n0 / D_;             // 0=q, 1=k, 2=v (uniform per CTA)
    __half* dst = (which == 0) ? qo : (which == 1) ? ko : vo;

#pragma unroll
    for (int mt = 0; mt < 4; mt++) {
#pragma unroll
        for (int nt = 0; nt < 4; nt++) {
            int m = m0 + wm + mt * 16 + (lane >> 2);
            int n = n0 + wn + nt * 8 + (lane & 3) * 2;
            float2 bv = *(const float2*)(bias + n);
            float2 v0 = {acc[mt][nt][0] + bv.x, acc[mt][nt][1] + bv.y};
            float2 v1 = {acc[mt][nt][2] + bv.x, acc[mt][nt][3] + bv.y};
            int b = m >> 10, sq = m & 1023;
            int nn = n - which * D_;
            int h = nn >> 6, d = nn & 63;
            int bh = b * H_ + h;
            if (which < 2) {
                size_t base = ((size_t)bh * S_ + sq) * HD_ + d;
                *(__half2*)(dst + base)           = __float22half2_rn(v0);
                *(__half2*)(dst + base + 8 * HD_) = __float22half2_rn(v1);
            } else {
                size_t r0 = ((size_t)bh * HD_ + d) * S_ + sq;
                dst[r0]          = __float2half_rn(v0.x);
                dst[r0 + S_]     = __float2half_rn(v0.y);
                dst[r0 + 8]      = __float2half_rn(v1.x);
                dst[r0 + S_ + 8] = __float2half_rn(v1.y);
            }
        }
    }
}

// ---------------------------------------------------------------------------
// Output projection GEMM: out[M, 768] fp32 = A2 @ Wo^T + bo
// ---------------------------------------------------------------------------
__global__ __launch_bounds__(256)
void tc_gemm_out(const __half* __restrict__ A,
                 const __half* __restrict__ W,
                 const float* __restrict__ bias,
                 float* __restrict__ outf)
{
    GEMM_PROLOGUE()

#pragma unroll
    for (int mt = 0; mt < 4; mt++) {
#pragma unroll
        for (int nt = 0; nt < 4; nt++) {
            int m = m0 + wm + mt * 16 + (lane >> 2);
            int n = n0 + wn + nt * 8 + (lane & 3) * 2;
            float2 bv = *(const float2*)(bias + n);
            float2 v0 = {acc[mt][nt][0] + bv.x, acc[mt][nt][1] + bv.y};
            float2 v1 = {acc[mt][nt][2] + bv.x, acc[mt][nt][3] + bv.y};
            *(float2*)(outf + (size_t)m * D_ + n) = v0;
            *(float2*)(outf + (size_t)(m + 8) * D_ + n) = v1;
        }
    }
}

// ---------------------------------------------------------------------------
// Tensor-core flash attention, fp16 operands.
// S = Q16 @ K16^T (1 pass). O = P16 @ V16 (1 pass).
// smem: Q plane 16KB + 2 stages x (K 8KB + Vt 8KB) = 48KB.
// Epilogue writes plain fp16 [M, 768] (O-proj A operand).
// ---------------------------------------------------------------------------
#define AST(s)  (16384 + (s) * 16384)
#define ATTN_SMEM 49152
#define SC_LOG2E 0.18033688f    // 0.125 * log2(e)

__global__ __launch_bounds__(256)
void attn_mma_kernel(const __half* __restrict__ Q,
                     const __half* __restrict__ K,
                     const __half* __restrict__ Vt,
                     __half* __restrict__ Ao)
{
    extern __shared__ char smem_raw[];
    const uint32_t sb = smem_u32(smem_raw);
    const int tid  = threadIdx.x;
    const int wid  = tid >> 5;
    const int lane = tid & 31;
    const int bh   = blockIdx.z * H_ + blockIdx.y;
    const int q0   = blockIdx.x * 128;

    // ---- Q load: 128 rows x 128B, 4 chunks/thread ----
    {
        int r  = tid >> 1;
        int lc = (tid & 1) * 4;
        const __half* qrow = Q + ((size_t)bh * S_ + q0 + r) * HD_;
#pragma unroll
        for (int c = 0; c < 4; c++) {
            uint32_t off = SW128((uint32_t)(r * 128 + (lc + c) * 16));
            cp_async16(sb + off, qrow + (lc + c) * 8);
        }
    }

    // KV stage loader: K 64x128B + Vt 64x128B, 4 chunks/thread
    auto load_kv = [&](int kt, int s) {
        int r  = tid >> 2;            // 0..63
        int c2 = (tid & 3) * 2;
        const __half* krow = K + ((size_t)bh * S_ + kt + r) * HD_;
        const __half* vrow = Vt + ((size_t)bh * HD_ + r) * S_ + kt;
        const uint32_t st = sb + AST(s);
#pragma unroll
        for (int cc = 0; cc < 2; cc++) {
            int c = c2 + cc;
            uint32_t off = SW128((uint32_t)(r * 128 + c * 16));
            cp_async16(st + off,        krow + c * 8);
            cp_async16(st + 8192 + off, vrow + c * 8);
        }
    };

    load_kv(0, 0);
    cp_commit();

    const int a_row = wid * 16 + (lane & 15);
    const int a_cb  = (lane >> 4) << 4;
    const int b_row = (lane & 7) + ((lane >> 4) << 3);
    const int b_cb  = ((lane >> 3) & 1) << 4;

    float m0 = -1e30f, m1 = -1e30f, l0 = 0.0f, l1 = 0.0f;
    float oacc[8][4];
#pragma unroll
    for (int j = 0; j < 8; j++)
#pragma unroll
        for (int e = 0; e < 4; e++) oacc[j][e] = 0.0f;

    for (int it = 0; it < S_ / 64; it++) {
        const int s = it & 1;
        if (it + 1 < S_ / 64) {
            load_kv((it + 1) * 64, s ^ 1);
            cp_commit();
            cp_wait<1>();
        } else {
            cp_wait<0>();
        }
        __syncthreads();

        const uint32_t stK = sb + AST(s);
        const uint32_t stV = stK + 8192;

        // ---- S = Q16 @ K16^T ----
        float sacc[8][4];
#pragma unroll
        for (int j = 0; j < 8; j++)
#pragma unroll
            for (int e = 0; e < 4; e++) sacc[j][e] = 0.0f;

#pragma unroll
        for (int ks = 0; ks < 4; ks++) {
            uint32_t bk[4][4], af[4];
#pragma unroll
            for (int nt2 = 0; nt2 < 4; nt2++) {
                uint32_t off = SW128((uint32_t)((b_row + nt2 * 16) * 128 + ks * 32 + b_cb));
                ldmatrix_x4(bk[nt2], stK + off);
            }
            uint32_t aoff = SW128((uint32_t)(a_row * 128 + ks * 32 + a_cb));
            ldmatrix_x4(af, sb + aoff);
#pragma unroll
            for (int j = 0; j < 8; j++)
                mma_f16(sacc[j], af, &bk[j >> 1][(j & 1) * 2]);
        }

        // ---- online softmax (exp2 domain, 1/8 scale folded) ----
        float mx0 = -1e30f, mx1 = -1e30f;
#pragma unroll
        for (int j = 0; j < 8; j++) {
            mx0 = fmaxf(mx0, fmaxf(sacc[j][0], sacc[j][1]));
            mx1 = fmaxf(mx1, fmaxf(sacc[j][2], sacc[j][3]));
        }
        mx0 = fmaxf(mx0, __shfl_xor_sync(0xffffffffu, mx0, 1));
        mx0 = fmaxf(mx0, __shfl_xor_sync(0xffffffffu, mx0, 2));
        mx1 = fmaxf(mx1, __shfl_xor_sync(0xffffffffu, mx1, 1));
        mx1 = fmaxf(mx1, __shfl_xor_sync(0xffffffffu, mx1, 2));
        float mn0 = fmaxf(m0, mx0), mn1 = fmaxf(m1, mx1);
        float corr0 = exp2f((m0 - mn0) * SC_LOG2E);
        float corr1 = exp2f((m1 - mn1) * SC_LOG2E);
        m0 = mn0; m1 = mn1;

        uint32_t pf[8][2];
        float rs0 = 0.0f, rs1 = 0.0f;
#pragma unroll
        for (int j = 0; j < 8; j++) {
            float p0 = exp2f((sacc[j][0] - m0) * SC_LOG2E);
            float p1 = exp2f((sacc[j][1] - m0) * SC_LOG2E);
            float p2 = exp2f((sacc[j][2] - m1) * SC_LOG2E);
            float p3 = exp2f((sacc[j][3] - m1) * SC_LOG2E);
            rs0 += p0 + p1;
            rs1 += p2 + p3;
            __half2 h01 = __float22half2_rn(make_float2(p0, p1));
            __half2 h23 = __float22half2_rn(make_float2(p2, p3));
            pf[j][0] = *(uint32_t*)&h01;
            pf[j][1] = *(uint32_t*)&h23;
        }
        rs0 += __shfl_xor_sync(0xffffffffu, rs0, 1);
        rs0 += __shfl_xor_sync(0xffffffffu, rs0, 2);
        rs1 += __shfl_xor_sync(0xffffffffu, rs1, 1);
        rs1 += __shfl_xor_sync(0xffffffffu, rs1, 2);
        l0 = l0 * corr0 + rs0;
        l1 = l1 * corr1 + rs1;
#pragma unroll
        for (int j = 0; j < 8; j++) {
            oacc[j][0] *= corr0; oacc[j][1] *= corr0;
            oacc[j][2] *= corr1; oacc[j][3] *= corr1;
        }

        // ---- O += P16 @ V16 ----
#pragma unroll
        for (int kc = 0; kc < 4; kc++) {
            uint32_t bv[4][4];
#pragma unroll
            for (int nt2 = 0; nt2 < 4; nt2++) {
                uint32_t off = SW128((uint32_t)((b_row + nt2 * 16) * 128 + kc * 32 + b_cb));
                ldmatrix_x4(bv[nt2], stV + off);
            }
            uint32_t ap[4] = {pf[2 * kc][0], pf[2 * kc][1], pf[2 * kc + 1][0], pf[2 * kc + 1][1]};
#pragma unroll
            for (int j = 0; j < 8; j++)
                mma_f16(oacc[j], ap, &bv[j >> 1][(j & 1) * 2]);
        }
        __syncthreads();
    }

    // ---- epilogue: write plain fp16 [M, 768] ----
    const int b = blockIdx.z, h = blockIdx.y;
    const float inv0 = 1.0f / l0, inv1 = 1.0f / l1;
    const int qr = q0 + wid * 16 + (lane >> 2);
    const int nc = h * HD_ + (lane & 3) * 2;
    __half* row0 = Ao + (size_t)(b * S_ + qr) * D_;
    __half* row1 = row0 + (size_t)8 * D_;
#pragma unroll
    for (int j = 0; j < 8; j++) {
        const int col = nc + j * 8;
        *(__half2*)(row0 + col) =
            __float22half2_rn(make_float2(oacc[j][0] * inv0, oacc[j][1] * inv0));
        *(__half2*)(row1 + col) =
            __float22half2_rn(make_float2(oacc[j][2] * inv1, oacc[j][3] * inv1));
    }
}

// ---------------------------------------------------------------------------
// Launch
// ---------------------------------------------------------------------------
extern "C" void kernel_launch(void* const* d_in, const int* in_sizes, int n_in,
                              void* d_out, int out_size)
{
    const float* x  = (const float*)d_in[0];
    const float* wq = (const float*)d_in[1];
    const float* bq = (const float*)d_in[2];
    const float* wk = (const float*)d_in[3];
    const float* bk = (const float*)d_in[4];
    const float* wv = (const float*)d_in[5];
    const float* bv = (const float*)d_in[6];
    const float* wo = (const float*)d_in[7];
    const float* bo = (const float*)d_in[8];
    float* out = (float*)d_out;

    __half *axp, *a2p, *wqkvp, *wop, *qhp, *khp, *vtp;
    float* bqkvp;
    cudaGetSymbolAddress((void**)&axp, g_ax);
    cudaGetSymbolAddress((void**)&a2p, g_a2);
    cudaGetSymbolAddress((void**)&wqkvp, g_wqkv);
    cudaGetSymbolAddress((void**)&wop, g_wo);
    cudaGetSymbolAddress((void**)&bqkvp, g_bqkv);
    cudaGetSymbolAddress((void**)&qhp, g_qh);
    cudaGetSymbolAddress((void**)&khp, g_kh);
    cudaGetSymbolAddress((void**)&vtp, g_vt);

    cudaFuncSetAttribute(attn_mma_kernel,
                         cudaFuncAttributeMaxDynamicSharedMemorySize, ATTN_SMEM);
    cudaFuncSetAttribute(tc_gemm_qkv,
                         cudaFuncAttributeMaxDynamicSharedMemorySize, GEMM_SMEM);
    cudaFuncSetAttribute(tc_gemm_out,
                         cudaFuncAttributeMaxDynamicSharedMemorySize, GEMM_SMEM);

    conv_a_kernel<<<(MTOT * D_ / 4) / 256, 256>>>(x, axp);
    conv_w_kernel<<<(D_ * D_ / 4) / 256, 256>>>(wq, wqkvp);
    conv_w_kernel<<<(D_ * D_ / 4) / 256, 256>>>(wk, wqkvp + (size_t)D_ * D_);
    conv_w_kernel<<<(D_ * D_ / 4) / 256, 256>>>(wv, wqkvp + (size_t)2 * D_ * D_);
    conv_w_kernel<<<(D_ * D_ / 4) / 256, 256>>>(wo, wop);
    concat_bias_kernel<<<(NQKV + 255) / 256, 256>>>(bq, bk, bv, bqkvp);

    tc_gemm_qkv<<<dim3(NQKV / 128, MTOT / 128), 256, GEMM_SMEM>>>(
        axp, wqkvp, bqkvp, qhp, khp, vtp);

    attn_mma_kernel<<<dim3(S_ / 128, H_, B_), 256, ATTN_SMEM>>>(qhp, khp, vtp, a2p);

    tc_gemm_out<<<dim3(D_ / 128, MTOT / 128), 256, GEMM_SMEM>>>(a2p, wop, bo, out);
}

// round 9
// speedup vs baseline: 7.6726x; 1.0298x over previous
#include <cuda_runtime.h>
#include <cuda_fp16.h>
#include <math.h>
#include <stdint.h>

// Problem constants
#define B_   8
#define S_   1024
#define D_   768
#define H_   12
#define HD_  64
#define BH_  (B_ * H_)       // 96
#define MTOT (B_ * S_)       // 8192
#define NQKV (3 * D_)        // 2304

// ---------------------------------------------------------------------------
// Scratch (device globals — no runtime allocation allowed)
// ---------------------------------------------------------------------------
__device__ __half g_ax[(size_t)MTOT * D_];        // fp16(x)
__device__ __half g_a2[(size_t)MTOT * D_];        // fp16(attn out)
__device__ __half g_wqkv[(size_t)NQKV * D_];      // fp16 W^T rows: [wq | wk | wv]
__device__ __half g_wo[(size_t)D_ * D_];          // fp16 wo^T [n, k]
__device__ float  g_bqkv[NQKV];                   // concat bias
__device__ __half g_qh[(size_t)BH_ * S_ * HD_];   // Q fp16 [bh, s, d]
__device__ __half g_kh[(size_t)BH_ * S_ * HD_];   // K fp16 [bh, s, d]
__device__ __half g_vt[(size_t)BH_ * HD_ * S_];   // V^T fp16 [bh, d, s]

// ---------------------------------------------------------------------------
// PTX helpers (standard sm_80+ instructions only)
// ---------------------------------------------------------------------------
__device__ __forceinline__ uint32_t smem_u32(const void* p) {
    uint32_t a;
    asm("{ .reg .u64 t; cvta.to.shared.u64 t, %1; cvt.u32.u64 %0, t; }" : "=r"(a) : "l"(p));
    return a;
}
__device__ __forceinline__ void cp_async16(uint32_t dst, const void* src) {
    asm volatile("cp.async.cg.shared.global [%0], [%1], 16;" :: "r"(dst), "l"(src) : "memory");
}
__device__ __forceinline__ void cp_commit() {
    asm volatile("cp.async.commit_group;" ::: "memory");
}
template <int N>
__device__ __forceinline__ void cp_wait() {
    asm volatile("cp.async.wait_group %0;" :: "n"(N) : "memory");
}
__device__ __forceinline__ void ldmatrix_x4(uint32_t* r, uint32_t addr) {
    asm volatile("ldmatrix.sync.aligned.m8n8.x4.shared.b16 {%0,%1,%2,%3}, [%4];"
        : "=r"(r[0]), "=r"(r[1]), "=r"(r[2]), "=r"(r[3]) : "r"(addr));
}
__device__ __forceinline__ void mma_f16(float* c, const uint32_t* a, const uint32_t* b) {
    asm volatile(
        "mma.sync.aligned.m16n8k16.row.col.f32.f16.f16.f32 "
        "{%0,%1,%2,%3}, {%4,%5,%6,%7}, {%8,%9}, {%0,%1,%2,%3};"
        : "+f"(c[0]), "+f"(c[1]), "+f"(c[2]), "+f"(c[3])
        : "r"(a[0]), "r"(a[1]), "r"(a[2]), "r"(a[3]), "r"(b[0]), "r"(b[1]));
}

// SW128 swizzle for 128B rows (16B-chunk granularity)
#define SW128(off) ((off) ^ (((off) >> 3) & 0x70))

// ---------------------------------------------------------------------------
// Conversion kernels
// ---------------------------------------------------------------------------
__global__ __launch_bounds__(256) void conv_a_kernel(const float* __restrict__ in,
                                                     __half* __restrict__ out)
{
    int idx = blockIdx.x * blockDim.x + threadIdx.x;   // one per 4 elems
    float4 x = *(const float4*)(in + (size_t)idx * 4);
    uint2 p;
    ((__half2*)&p)[0] = __float22half2_rn(make_float2(x.x, x.y));
    ((__half2*)&p)[1] = __float22half2_rn(make_float2(x.z, x.w));
    *(uint2*)(out + (size_t)idx * 4) = p;
}

// All 4 weights in one launch, coalesced both sides via 32x32 smem transpose.
// z = 0..3 selects (wq, wk, wv, wo); output [n, k] fp16.
__global__ __launch_bounds__(256)
void conv_w4_kernel(const float* __restrict__ wq, const float* __restrict__ wk,
                    const float* __restrict__ wv, const float* __restrict__ wo,
                    __half* __restrict__ wqkv, __half* __restrict__ woo)
{
    __shared__ float tile[32][33];
    const int z = blockIdx.z;
    const float* w = (z == 0) ? wq : (z == 1) ? wk : (z == 2) ? wv : wo;
    __half* dst = (z < 3) ? wqkv + (size_t)z * D_ * D_ : woo;
    const int k0 = blockIdx.y * 32, n0 = blockIdx.x * 32;
    const int tr = threadIdx.x >> 3;
    const int tc = (threadIdx.x & 7) * 4;

    float4 v = *(const float4*)(w + (size_t)(k0 + tr) * D_ + n0 + tc);
    tile[tr][tc + 0] = v.x; tile[tr][tc + 1] = v.y;
    tile[tr][tc + 2] = v.z; tile[tr][tc + 3] = v.w;
    __syncthreads();

    uint2 p;
    ((__half2*)&p)[0] = __float22half2_rn(make_float2(tile[tc + 0][tr], tile[tc + 1][tr]));
    ((__half2*)&p)[1] = __float22half2_rn(make_float2(tile[tc + 2][tr], tile[tc + 3][tr]));
    *(uint2*)(dst + (size_t)(n0 + tr) * D_ + k0 + tc) = p;
}

__global__ void concat_bias_kernel(const float* __restrict__ bq,
                                   const float* __restrict__ bk,
                                   const float* __restrict__ bv,
                                   float* __restrict__ out)
{
    int i = blockIdx.x * blockDim.x + threadIdx.x;
    if (i < NQKV)
        out[i] = (i < D_) ? bq[i] : (i < 2 * D_ ? bk[i - D_] : bv[i - 2 * D_]);
}

// ---------------------------------------------------------------------------
// Common GEMM skeleton: CTA 128x128, BK=64, K=768 (12 iters),
// 3-stage cp.async pipeline, ONE __syncthreads per iter,
// 8 warps (2m x 4n), warp tile 64x32, fp16 mma -> fp32.
// ---------------------------------------------------------------------------
#define BK_        64
#define NT_        (D_ / BK_)             // 12
#define TILE_B     (128 * 128)            // 16KB
#define GEMM_SMEM  (3 * 2 * TILE_B)       // 96KB (3 stages x (A+B))

#define GEMM_PROLOGUE()                                                       \
    extern __shared__ char smem_raw[];                                        \
    const uint32_t sbase = smem_u32(smem_raw);                                \
    const int tid  = threadIdx.x;                                             \
    const int wid  = tid >> 5;                                                \
    const int lane = tid & 31;                                                \
    const int wm   = (wid & 1) * 64;                                          \
    const int wn   = (wid >> 1) * 32;                                         \
    const int m0   = blockIdx.y * 128;                                        \
    const int n0   = blockIdx.x * 128;                                        \
    const int lr = tid >> 1;                                                  \
    const int lc = (tid & 1) * 4;                                             \
    float acc[4][4][4];                                                       \
    _Pragma("unroll")                                                         \
    for (int i = 0; i < 4; i++)                                               \
        _Pragma("unroll")                                                     \
        for (int j = 0; j < 4; j++)                                           \
            _Pragma("unroll")                                                 \
            for (int e = 0; e < 4; e++) acc[i][j][e] = 0.0f;                  \
    auto load_stage = [&](int it, int s) {                                    \
        const uint32_t sA = sbase + s * 2 * TILE_B;                           \
        const uint32_t sB = sA + TILE_B;                                      \
        const int k0 = it * BK_;                                              \
        const __half* Ag = A + (size_t)(m0 + lr) * D_ + k0 + lc * 8;          \
        const __half* Wg = W + (size_t)(n0 + lr) * D_ + k0 + lc * 8;          \
        _Pragma("unroll")                                                     \
        for (int c = 0; c < 4; c++) {                                         \
            uint32_t off = SW128((uint32_t)(lr * 128 + (lc + c) * 16));       \
            cp_async16(sA + off, Ag + c * 8);                                 \
            cp_async16(sB + off, Wg + c * 8);                                 \
        }                                                                     \
    };                                                                        \
    load_stage(0, 0);                                                         \
    cp_commit();                                                              \
    load_stage(1, 1);                                                         \
    cp_commit();                                                              \
    const int a_row = wm + (lane & 15);                                       \
    const int a_cb  = (lane >> 4) << 4;                                       \
    const int b_row = wn + (lane & 7) + ((lane >> 4) << 3);                   \
    const int b_cb  = ((lane >> 3) & 1) << 4;                                 \
    for (int it = 0; it < NT_; it++) {                                        \
        const int s = it % 3;                                                 \
        if (it < NT_ - 1) cp_wait<1>(); else cp_wait<0>();                    \
        __syncthreads();                                                      \
        if (it + 2 < NT_) {                                                   \
            load_stage(it + 2, (it + 2) % 3);                                 \
            cp_commit();                                                      \
        }                                                                     \
        const uint32_t sA = sbase + s * 2 * TILE_B;                           \
        const uint32_t sB = sA + TILE_B;                                      \
        _Pragma("unroll")                                                     \
        for (int ks = 0; ks < BK_ / 16; ks++) {                               \
            uint32_t af[4][4], bf[2][4];                                      \
            _Pragma("unroll")                                                 \
            for (int mt = 0; mt < 4; mt++) {                                  \
                uint32_t off = SW128((uint32_t)((a_row + mt * 16) * 128 + ks * 32 + a_cb)); \
                ldmatrix_x4(af[mt], sA + off);                                \
            }                                                                 \
            _Pragma("unroll")                                                 \
            for (int nt2 = 0; nt2 < 2; nt2++) {                               \
                uint32_t off = SW128((uint32_t)((b_row + nt2 * 16) * 128 + ks * 32 + b_cb)); \
                ldmatrix_x4(bf[nt2], sB + off);                               \
            }                                                                 \
            _Pragma("unroll")                                                 \
            for (int mt = 0; mt < 4; mt++)                                    \
                _Pragma("unroll")                                             \
                for (int nt = 0; nt < 4; nt++)                                \
                    mma_f16(acc[mt][nt], af[mt], &bf[nt >> 1][(nt & 1) * 2]); \
        }                                                                     \
    }

// ---------------------------------------------------------------------------
// Fused QKV GEMM: C[M, 2304] = Ax @ Wqkv^T + bqkv, scattered to Q/K fp16
// [bh,s,d] and V^T fp16 [bh,d,s]. `which` is uniform per CTA (128 | 768).
// ---------------------------------------------------------------------------
__global__ __launch_bounds__(256)
void tc_gemm_qkv(const __half* __restrict__ A,
                 const __half* __restrict__ W,
                 const float* __restrict__ bias,
                 __half* __restrict__ qo, __half* __restrict__ ko,
                 __half* __restrict__ vo)
{
    GEMM_PROLOGUE()

    const int which = n0 / D_;             // 0=q, 1=k, 2=v (uniform per CTA)
    __half* dst = (which == 0) ? qo : (which == 1) ? ko : vo;

#pragma unroll
    for (int mt = 0; mt < 4; mt++) {
#pragma unroll
        for (int nt = 0; nt < 4; nt++) {
            int m = m0 + wm + mt * 16 + (lane >> 2);
            int n = n0 + wn + nt * 8 + (lane & 3) * 2;
            float2 bv = *(const float2*)(bias + n);
            float2 v0 = {acc[mt][nt][0] + bv.x, acc[mt][nt][1] + bv.y};
            float2 v1 = {acc[mt][nt][2] + bv.x, acc[mt][nt][3] + bv.y};
            int b = m >> 10, sq = m & 1023;
            int nn = n - which * D_;
            int h = nn >> 6, d = nn & 63;
            int bh = b * H_ + h;
            if (which < 2) {
                size_t base = ((size_t)bh * S_ + sq) * HD_ + d;
                *(__half2*)(dst + base)           = __float22half2_rn(v0);
                *(__half2*)(dst + base + 8 * HD_) = __float22half2_rn(v1);
            } else {
                size_t r0 = ((size_t)bh * HD_ + d) * S_ + sq;
                dst[r0]          = __float2half_rn(v0.x);
                dst[r0 + S_]     = __float2half_rn(v0.y);
                dst[r0 + 8]      = __float2half_rn(v1.x);
                dst[r0 + S_ + 8] = __float2half_rn(v1.y);
            }
        }
    }
}

// ---------------------------------------------------------------------------
// Output projection GEMM: out[M, 768] fp32 = A2 @ Wo^T + bo
// ---------------------------------------------------------------------------
__global__ __launch_bounds__(256)
void tc_gemm_out(const __half* __restrict__ A,
                 const __half* __restrict__ W,
                 const float* __restrict__ bias,
                 float* __restrict__ outf)
{
    GEMM_PROLOGUE()

#pragma unroll
    for (int mt = 0; mt < 4; mt++) {
#pragma unroll
        for (int nt = 0; nt < 4; nt++) {
            int m = m0 + wm + mt * 16 + (lane >> 2);
            int n = n0 + wn + nt * 8 + (lane & 3) * 2;
            float2 bv = *(const float2*)(bias + n);
            float2 v0 = {acc[mt][nt][0] + bv.x, acc[mt][nt][1] + bv.y};
            float2 v1 = {acc[mt][nt][2] + bv.x, acc[mt][nt][3] + bv.y};
            *(float2*)(outf + (size_t)m * D_ + n) = v0;
            *(float2*)(outf + (size_t)(m + 8) * D_ + n) = v1;
        }
    }
}

// ---------------------------------------------------------------------------
// Tensor-core flash attention, fp16 operands, 3-stage KV pipeline.
// S = Q16 @ K16^T (1 pass). O = P16 @ V16 (1 pass).
// smem: Q plane 16KB + 3 stages x (K 8KB + Vt 8KB) = 64KB.
// Epilogue writes plain fp16 [M, 768] (O-proj A operand).
// ---------------------------------------------------------------------------
#define AST(s)  (16384 + (s) * 16384)
#define ATTN_SMEM 65536
#define NKV_    (S_ / 64)       // 16
#define SC_LOG2E 0.18033688f    // 0.125 * log2(e)

__global__ __launch_bounds__(256)
void attn_mma_kernel(const __half* __restrict__ Q,
                     const __half* __restrict__ K,
                     const __half* __restrict__ Vt,
                     __half* __restrict__ Ao)
{
    extern __shared__ char smem_raw[];
    const uint32_t sb = smem_u32(smem_raw);
    const int tid  = threadIdx.x;
    const int wid  = tid >> 5;
    const int lane = tid & 31;
    const int bh   = blockIdx.z * H_ + blockIdx.y;
    const int q0   = blockIdx.x * 128;

    // ---- Q load: 128 rows x 128B, 4 chunks/thread ----
    {
        int r  = tid >> 1;
        int lc = (tid & 1) * 4;
        const __half* qrow = Q + ((size_t)bh * S_ + q0 + r) * HD_;
#pragma unroll
        for (int c = 0; c < 4; c++) {
            uint32_t off = SW128((uint32_t)(r * 128 + (lc + c) * 16));
            cp_async16(sb + off, qrow + (lc + c) * 8);
        }
    }

    // KV stage loader: K 64x128B + Vt 64x128B, 4 chunks/thread
    auto load_kv = [&](int kt, int s) {
        int r  = tid >> 2;            // 0..63
        int c2 = (tid & 3) * 2;
        const __half* krow = K + ((size_t)bh * S_ + kt + r) * HD_;
        const __half* vrow = Vt + ((size_t)bh * HD_ + r) * S_ + kt;
        const uint32_t st = sb + AST(s);
#pragma unroll
        for (int cc = 0; cc < 2; cc++) {
            int c = c2 + cc;
            uint32_t off = SW128((uint32_t)(r * 128 + c * 16));
            cp_async16(st + off,        krow + c * 8);
            cp_async16(st + 8192 + off, vrow + c * 8);
        }
    };

    load_kv(0, 0);
    cp_commit();                 // group 0: Q + KV0
    load_kv(64, 1);
    cp_commit();                 // group 1: KV1

    const int a_row = wid * 16 + (lane & 15);
    const int a_cb  = (lane >> 4) << 4;
    const int b_row = (lane & 7) + ((lane >> 4) << 3);
    const int b_cb  = ((lane >> 3) & 1) << 4;

    float m0 = -1e30f, m1 = -1e30f, l0 = 0.0f, l1 = 0.0f;
    float oacc[8][4];
#pragma unroll
    for (int j = 0; j < 8; j++)
#pragma unroll
        for (int e = 0; e < 4; e++) oacc[j][e] = 0.0f;

    for (int it = 0; it < NKV_; it++) {
        const int s = it % 3;
        if (it < NKV_ - 1) cp_wait<1>(); else cp_wait<0>();
        __syncthreads();
        if (it + 2 < NKV_) {
            load_kv((it + 2) * 64, (it + 2) % 3);
            cp_commit();
        }

        const uint32_t stK = sb + AST(s);
        const uint32_t stV = stK + 8192;

        // ---- S = Q16 @ K16^T ----
        float sacc[8][4];
#pragma unroll
        for (int j = 0; j < 8; j++)
#pragma unroll
            for (int e = 0; e < 4; e++) sacc[j][e] = 0.0f;

#pragma unroll
        for (int ks = 0; ks < 4; ks++) {
            uint32_t bk[4][4], af[4];
#pragma unroll
            for (int nt2 = 0; nt2 < 4; nt2++) {
                uint32_t off = SW128((uint32_t)((b_row + nt2 * 16) * 128 + ks * 32 + b_cb));
                ldmatrix_x4(bk[nt2], stK + off);
            }
            uint32_t aoff = SW128((uint32_t)(a_row * 128 + ks * 32 + a_cb));
            ldmatrix_x4(af, sb + aoff);
#pragma unroll
            for (int j = 0; j < 8; j++)
                mma_f16(sacc[j], af, &bk[j >> 1][(j & 1) * 2]);
        }

        // ---- online softmax (exp2 domain, 1/8 scale folded) ----
        float mx0 = -1e30f, mx1 = -1e30f;
#pragma unroll
        for (int j = 0; j < 8; j++) {
            mx0 = fmaxf(mx0, fmaxf(sacc[j][0], sacc[j][1]));
            mx1 = fmaxf(mx1, fmaxf(sacc[j][2], sacc[j][3]));
        }
        mx0 = fmaxf(mx0, __shfl_xor_sync(0xffffffffu, mx0, 1));
        mx0 = fmaxf(mx0, __shfl_xor_sync(0xffffffffu, mx0, 2));
        mx1 = fmaxf(mx1, __shfl_xor_sync(0xffffffffu, mx1, 1));
        mx1 = fmaxf(mx1, __shfl_xor_sync(0xffffffffu, mx1, 2));
        float mn0 = fmaxf(m0, mx0), mn1 = fmaxf(m1, mx1);
        float corr0 = exp2f((m0 - mn0) * SC_LOG2E);
        float corr1 = exp2f((m1 - mn1) * SC_LOG2E);
        m0 = mn0; m1 = mn1;

        uint32_t pf[8][2];
        float rs0 = 0.0f, rs1 = 0.0f;
#pragma unroll
        for (int j = 0; j < 8; j++) {
            float p0 = exp2f((sacc[j][0] - m0) * SC_LOG2E);
            float p1 = exp2f((sacc[j][1] - m0) * SC_LOG2E);
            float p2 = exp2f((sacc[j][2] - m1) * SC_LOG2E);
            float p3 = exp2f((sacc[j][3] - m1) * SC_LOG2E);
            rs0 += p0 + p1;
            rs1 += p2 + p3;
            __half2 h01 = __float22half2_rn(make_float2(p0, p1));
            __half2 h23 = __float22half2_rn(make_float2(p2, p3));
            pf[j][0] = *(uint32_t*)&h01;
            pf[j][1] = *(uint32_t*)&h23;
        }
        rs0 += __shfl_xor_sync(0xffffffffu, rs0, 1);
        rs0 += __shfl_xor_sync(0xffffffffu, rs0, 2);
        rs1 += __shfl_xor_sync(0xffffffffu, rs1, 1);
        rs1 += __shfl_xor_sync(0xffffffffu, rs1, 2);
        l0 = l0 * corr0 + rs0;
        l1 = l1 * corr1 + rs1;
#pragma unroll
        for (int j = 0; j < 8; j++) {
            oacc[j][0] *= corr0; oacc[j][1] *= corr0;
            oacc[j][2] *= corr1; oacc[j][3] *= corr1;
        }

        // ---- O += P16 @ V16 ----
#pragma unroll
        for (int kc = 0; kc < 4; kc++) {
            uint32_t bv[4][4];
#pragma unroll
            for (int nt2 = 0; nt2 < 4; nt2++) {
                uint32_t off = SW128((uint32_t)((b_row + nt2 * 16) * 128 + kc * 32 + b_cb));
                ldmatrix_x4(bv[nt2], stV + off);
            }
            uint32_t ap[4] = {pf[2 * kc][0], pf[2 * kc][1], pf[2 * kc + 1][0], pf[2 * kc + 1][1]};
#pragma unroll
            for (int j = 0; j < 8; j++)
                mma_f16(oacc[j], ap, &bv[j >> 1][(j & 1) * 2]);
        }
    }

    // ---- epilogue: write plain fp16 [M, 768] ----
    const int b = blockIdx.z, h = blockIdx.y;
    const float inv0 = 1.0f / l0, inv1 = 1.0f / l1;
    const int qr = q0 + wid * 16 + (lane >> 2);
    const int nc = h * HD_ + (lane & 3) * 2;
    __half* row0 = Ao + (size_t)(b * S_ + qr) * D_;
    __half* row1 = row0 + (size_t)8 * D_;
#pragma unroll
    for (int j = 0; j < 8; j++) {
        const int col = nc + j * 8;
        *(__half2*)(row0 + col) =
            __float22half2_rn(make_float2(oacc[j][0] * inv0, oacc[j][1] * inv0));
        *(__half2*)(row1 + col) =
            __float22half2_rn(make_float2(oacc[j][2] * inv1, oacc[j][3] * inv1));
    }
}

// ---------------------------------------------------------------------------
// Launch
// ---------------------------------------------------------------------------
extern "C" void kernel_launch(void* const* d_in, const int* in_sizes, int n_in,
                              void* d_out, int out_size)
{
    const float* x  = (const float*)d_in[0];
    const float* wq = (const float*)d_in[1];
    const float* bq = (const float*)d_in[2];
    const float* wk = (const float*)d_in[3];
    const float* bk = (const float*)d_in[4];
    const float* wv = (const float*)d_in[5];
    const float* bv = (const float*)d_in[6];
    const float* wo = (const float*)d_in[7];
    const float* bo = (const float*)d_in[8];
    float* out = (float*)d_out;

    __half *axp, *a2p, *wqkvp, *wop, *qhp, *khp, *vtp;
    float* bqkvp;
    cudaGetSymbolAddress((void**)&axp, g_ax);
    cudaGetSymbolAddress((void**)&a2p, g_a2);
    cudaGetSymbolAddress((void**)&wqkvp, g_wqkv);
    cudaGetSymbolAddress((void**)&wop, g_wo);
    cudaGetSymbolAddress((void**)&bqkvp, g_bqkv);
    cudaGetSymbolAddress((void**)&qhp, g_qh);
    cudaGetSymbolAddress((void**)&khp, g_kh);
    cudaGetSymbolAddress((void**)&vtp, g_vt);

    cudaFuncSetAttribute(attn_mma_kernel,
                         cudaFuncAttributeMaxDynamicSharedMemorySize, ATTN_SMEM);
    cudaFuncSetAttribute(tc_gemm_qkv,
                         cudaFuncAttributeMaxDynamicSharedMemorySize, GEMM_SMEM);
    cudaFuncSetAttribute(tc_gemm_out,
                         cudaFuncAttributeMaxDynamicSharedMemorySize, GEMM_SMEM);

    conv_a_kernel<<<(MTOT * D_ / 4) / 256, 256>>>(x, axp);
    conv_w4_kernel<<<dim3(D_ / 32, D_ / 32, 4), 256>>>(wq, wk, wv, wo, wqkvp, wop);
    concat_bias_kernel<<<(NQKV + 255) / 256, 256>>>(bq, bk, bv, bqkvp);

    tc_gemm_qkv<<<dim3(NQKV / 128, MTOT / 128), 256, GEMM_SMEM>>>(
        axp, wqkvp, bqkvp, qhp, khp, vtp);

    attn_mma_kernel<<<dim3(S_ / 128, H_, B_), 256, ATTN_SMEM>>>(qhp, khp, vtp, a2p);

    tc_gemm_out<<<dim3(D_ / 128, MTOT / 128), 256, GEMM_SMEM>>>(a2p, wop, bo, out);
}